// round 12
// baseline (speedup 1.0000x reference)
#include <cuda_runtime.h>
#include <cuda_bf16.h>
#include <cuda_fp8.h>
#include <cstdint>
#include <math.h>

#define N_PTS 8192
#define DIM   2048
#define NCLS  751
#define KNN   6
#define CAND  16
#define GIN_ONE_PLUS_EPS 1.3f
#define BN_EPS 1e-5f
#define FP8_SCALE 256.0f
#define LO_SCALE 2048.0f
#define INV_LO_SCALE (1.0f / 2048.0f)

// ---------------- scratch ----------------------------------------------------
__device__ float g_xn [(size_t)N_PTS * DIM];
__device__ unsigned char g_x8 [(size_t)N_PTS * DIM];      // e4m3 of xn*256
__device__ unsigned short g_sim[(size_t)N_PTS * N_PTS];   // bf16 sims; later fp32 temp C
__device__ int   g_cand[(size_t)N_PTS * CAND];
__device__ int   g_idx[(size_t)N_PTS * KNN];
__device__ float g_h2 [(size_t)N_PTS * DIM];
__device__ unsigned short g_sh [(size_t)N_PTS * DIM];     // act bf16 hi (h0, later hn)
__device__ unsigned short g_th [(size_t)N_PTS * DIM];     // h1 bf16 hi
__device__ unsigned char g_a8 [(size_t)N_PTS * DIM];      // act e4m3(v)     (h0 / hn)
__device__ unsigned char g_a8l[(size_t)N_PTS * DIM];      // act e4m3(lo*2048)
__device__ unsigned char g_b8 [(size_t)N_PTS * DIM];      // h1 e4m3(v)
__device__ unsigned char g_b8l[(size_t)N_PTS * DIM];      // h1 e4m3(lo*2048)
__device__ unsigned short g_w1h[(size_t)DIM * DIM], g_w2h[(size_t)DIM * DIM];
__device__ unsigned short g_wch[(size_t)NCLS * DIM];
__device__ unsigned char g_w18 [(size_t)DIM * DIM], g_w18l[(size_t)DIM * DIM];
__device__ unsigned char g_w28 [(size_t)DIM * DIM], g_w28l[(size_t)DIM * DIM];
__device__ unsigned char g_wc8 [(size_t)NCLS * DIM], g_wc8l[(size_t)NCLS * DIM];
__device__ float g_scale[DIM];
__device__ float g_shift[DIM];

// ---------------- helpers ----------------------------------------------------
__device__ __forceinline__ uint32_t smem_to_u32(const void* p) {
    uint32_t a;
    asm("{ .reg .u64 t; cvta.to.shared.u64 t, %1; cvt.u32.u64 %0, t; }" : "=r"(a) : "l"(p));
    return a;
}

__device__ __forceinline__ void cp_async16(uint32_t dst, const void* src, int valid) {
    asm volatile("cp.async.cg.shared.global [%0], [%1], 16, %2;"
                 :: "r"(dst), "l"(src), "r"(valid ? 16 : 0) : "memory");
}
__device__ __forceinline__ void cp_commit() {
    asm volatile("cp.async.commit_group;" ::: "memory");
}
template <int N>
__device__ __forceinline__ void cp_wait() {
    asm volatile("cp.async.wait_group %0;" :: "n"(N) : "memory");
}

__device__ __forceinline__ void ldm_x4(uint32_t* r, uint32_t addr) {
    asm volatile("ldmatrix.sync.aligned.m8n8.x4.shared.b16 {%0,%1,%2,%3}, [%4];"
                 : "=r"(r[0]), "=r"(r[1]), "=r"(r[2]), "=r"(r[3]) : "r"(addr));
}

__device__ __forceinline__ void mma16816(float* d, const uint32_t* a, uint32_t b0, uint32_t b1) {
    asm volatile("mma.sync.aligned.m16n8k16.row.col.f32.bf16.bf16.f32 "
                 "{%0,%1,%2,%3}, {%4,%5,%6,%7}, {%8,%9}, {%0,%1,%2,%3};"
                 : "+f"(d[0]), "+f"(d[1]), "+f"(d[2]), "+f"(d[3])
                 : "r"(a[0]), "r"(a[1]), "r"(a[2]), "r"(a[3]), "r"(b0), "r"(b1));
}

__device__ __forceinline__ void mma16832_fp8(float* d, const uint32_t* a, uint32_t b0, uint32_t b1) {
    asm volatile("mma.sync.aligned.m16n8k32.row.col.f32.e4m3.e4m3.f32 "
                 "{%0,%1,%2,%3}, {%4,%5,%6,%7}, {%8,%9}, {%0,%1,%2,%3};"
                 : "+f"(d[0]), "+f"(d[1]), "+f"(d[2]), "+f"(d[3])
                 : "r"(a[0]), "r"(a[1]), "r"(a[2]), "r"(a[3]), "r"(b0), "r"(b1));
}

__device__ __forceinline__ unsigned char to_e4m3(float v) {
    return (unsigned char)__nv_cvt_float_to_fp8(v, __NV_SATFINITE, __NV_E4M3);
}

// bf16 bit pattern -> order-preserving 16-bit key (bigger = larger value)
__device__ __forceinline__ uint32_t sortable16(uint32_t us) {
    return (us & 0x8000u) ? (~us & 0xFFFFu) : (us | 0x8000u);
}

#define SMEM_GEMM 66048

// ---------------- fp8 similarity GEMM: C = X*X^T (bf16 out, raw scale) -------
__global__ __launch_bounds__(128, 2)
void sim_fp8(const unsigned char* __restrict__ X, unsigned short* __restrict__ C)
{
    const int bx = blockIdx.x, by = blockIdx.y;
    if (bx > by) return;

    extern __shared__ char smem[];
    const uint32_t sb = smem_to_u32(smem);
    const int tid = threadIdx.x;
    const int lane = tid & 31;
    const int wid = tid >> 5;
    const int wm = wid & 1;
    const int wn = wid >> 1;
    const int wRow = wm * 64, wCol = wn * 64;

    const int rowBase = by * 128;
    const int colBase = bx * 128;
    const int nchunk = DIM / 128;

    float acc[4][8][4];
#pragma unroll
    for (int i = 0; i < 4; ++i)
#pragma unroll
        for (int j = 0; j < 8; ++j)
#pragma unroll
            for (int q = 0; q < 4; ++q) acc[i][j][q] = 0.f;

    auto load_chunk = [&](int c) {
        const int k0 = c * 128;
        const uint32_t base = sb + (uint32_t)(c & 1) * 32768u;
#pragma unroll
        for (int i = 0; i < 8; ++i) {
            const int u = tid + i * 128;
            const int r = u >> 3, ku = u & 7;
            cp_async16(base + (uint32_t)(r * 8 + (ku ^ (r & 7))) * 16,
                       X + (size_t)(rowBase + r) * DIM + k0 + ku * 16, 1);
        }
#pragma unroll
        for (int i = 0; i < 8; ++i) {
            const int u = tid + i * 128;
            const int r = u >> 3, ku = u & 7;
            cp_async16(base + 16384u + (uint32_t)(r * 8 + (ku ^ (r & 7))) * 16,
                       X + (size_t)(colBase + r) * DIM + k0 + ku * 16, 1);
        }
        cp_commit();
    };

    load_chunk(0);

    for (int c = 0; c < nchunk; ++c) {
        if (c + 1 < nchunk) { load_chunk(c + 1); cp_wait<1>(); }
        else                { cp_wait<0>(); }
        __syncthreads();

        const uint32_t base = sb + (uint32_t)(c & 1) * 32768u;
#pragma unroll
        for (int s = 0; s < 4; ++s) {
            uint32_t a[4][4];
#pragma unroll
            for (int i = 0; i < 4; ++i) {
                const int r = wRow + i * 16 + (lane & 15);
                const int ku = s * 2 + (lane >> 4);
                ldm_x4(a[i], base + (uint32_t)(r * 8 + (ku ^ (r & 7))) * 16);
            }
            uint32_t bf[4][4];
#pragma unroll
            for (int j = 0; j < 4; ++j) {
                const int rn = wCol + j * 16 + (lane & 7) + ((lane >> 4) << 3);
                const int ku = s * 2 + ((lane >> 3) & 1);
                ldm_x4(bf[j], base + 16384u + (uint32_t)(rn * 8 + (ku ^ (rn & 7))) * 16);
            }
#pragma unroll
            for (int i = 0; i < 4; ++i)
#pragma unroll
                for (int j = 0; j < 4; ++j) {
                    mma16832_fp8(acc[i][j * 2 + 0], a[i], bf[j][0], bf[j][1]);
                    mma16832_fp8(acc[i][j * 2 + 1], a[i], bf[j][2], bf[j][3]);
                }
        }
        __syncthreads();
    }

#pragma unroll
    for (int i = 0; i < 4; ++i) {
        const int row = rowBase + wRow + i * 16 + (lane >> 2);
#pragma unroll
        for (int j = 0; j < 8; ++j) {
            const int col = colBase + wCol + j * 8 + (lane & 3) * 2;
#pragma unroll
            for (int h = 0; h < 2; ++h) {
                const int rr = row + h * 8;
                __nv_bfloat16 b0 = __float2bfloat16(acc[i][j][h * 2 + 0]);
                __nv_bfloat16 b1 = __float2bfloat16(acc[i][j][h * 2 + 1]);
                uint32_t pk = (uint32_t)(*(unsigned short*)&b0) |
                              ((uint32_t)(*(unsigned short*)&b1) << 16);
                *(uint32_t*)(C + (size_t)rr * N_PTS + col) = pk;
            }
        }
    }

    if (bx < by) {
        __syncthreads();
        float* sc = (float*)smem;
#pragma unroll
        for (int i = 0; i < 4; ++i) {
            const int lr = wRow + i * 16 + (lane >> 2);
#pragma unroll
            for (int j = 0; j < 8; ++j) {
                const int lc = wCol + j * 8 + (lane & 3) * 2;
                sc[(lr    ) * 129 + lc    ] = acc[i][j][0];
                sc[(lr    ) * 129 + lc + 1] = acc[i][j][1];
                sc[(lr + 8) * 129 + lc    ] = acc[i][j][2];
                sc[(lr + 8) * 129 + lc + 1] = acc[i][j][3];
            }
        }
        __syncthreads();
        for (int cc = 0; cc < 128; ++cc) {
            __nv_bfloat16 b = __float2bfloat16(sc[tid * 129 + cc]);
            C[(size_t)(colBase + cc) * N_PTS + rowBase + tid] = *(unsigned short*)&b;
        }
    }
}

// ---------------- bf16 single-pass GEMM: C = Ah*Bh^T + bias (fp32 out) -------
__global__ __launch_bounds__(128, 2)
void gemm_main(const __nv_bfloat16* __restrict__ Ah, const __nv_bfloat16* __restrict__ Bh,
               float* __restrict__ Cf, int M, int Nc, int Kd,
               const float* __restrict__ bias)
{
    const int bx = blockIdx.x, by = blockIdx.y;
    extern __shared__ char smem[];
    const uint32_t sb = smem_to_u32(smem);
    const int tid = threadIdx.x;
    const int lane = tid & 31;
    const int wid = tid >> 5;
    const int wm = wid & 1;
    const int wn = wid >> 1;
    const int wRow = wm * 64, wCol = wn * 64;

    const int rowBase = by * 128;
    const int colBase = bx * 128;
    const int nchunk = Kd / 64;

    float acc[4][8][4];
#pragma unroll
    for (int i = 0; i < 4; ++i)
#pragma unroll
        for (int j = 0; j < 8; ++j)
#pragma unroll
            for (int q = 0; q < 4; ++q) acc[i][j][q] = 0.f;

    auto load_chunk = [&](int c) {
        const int k0 = c * 64;
        const uint32_t base = sb + (uint32_t)(c & 1) * 32768u;
#pragma unroll
        for (int i = 0; i < 8; ++i) {
            const int u = tid + i * 128;
            const int r = u >> 3, ku = u & 7;
            const int grow = rowBase + r;
            cp_async16(base + (uint32_t)(r * 8 + (ku ^ (r & 7))) * 16,
                       Ah + (size_t)grow * Kd + k0 + ku * 8, grow < M);
        }
#pragma unroll
        for (int i = 0; i < 8; ++i) {
            const int u = tid + i * 128;
            const int r = u >> 3, ku = u & 7;
            const int grow = colBase + r;
            cp_async16(base + 16384u + (uint32_t)(r * 8 + (ku ^ (r & 7))) * 16,
                       Bh + (size_t)grow * Kd + k0 + ku * 8, grow < Nc);
        }
        cp_commit();
    };

    load_chunk(0);

    for (int c = 0; c < nchunk; ++c) {
        if (c + 1 < nchunk) { load_chunk(c + 1); cp_wait<1>(); }
        else                { cp_wait<0>(); }
        __syncthreads();

        const uint32_t base = sb + (uint32_t)(c & 1) * 32768u;
#pragma unroll
        for (int s = 0; s < 4; ++s) {
            uint32_t a[4][4];
#pragma unroll
            for (int i = 0; i < 4; ++i) {
                const int r = wRow + i * 16 + (lane & 15);
                const int ku = s * 2 + (lane >> 4);
                ldm_x4(a[i], base + (uint32_t)(r * 8 + (ku ^ (r & 7))) * 16);
            }
            uint32_t bf[4][4];
#pragma unroll
            for (int j = 0; j < 4; ++j) {
                const int rn = wCol + j * 16 + (lane & 7) + ((lane >> 4) << 3);
                const int ku = s * 2 + ((lane >> 3) & 1);
                ldm_x4(bf[j], base + 16384u + (uint32_t)(rn * 8 + (ku ^ (rn & 7))) * 16);
            }
#pragma unroll
            for (int i = 0; i < 4; ++i)
#pragma unroll
                for (int j = 0; j < 4; ++j) {
                    mma16816(acc[i][j * 2 + 0], a[i], bf[j][0], bf[j][1]);
                    mma16816(acc[i][j * 2 + 1], a[i], bf[j][2], bf[j][3]);
                }
        }
        __syncthreads();
    }

#pragma unroll
    for (int i = 0; i < 4; ++i) {
        const int row = rowBase + wRow + i * 16 + (lane >> 2);
#pragma unroll
        for (int j = 0; j < 8; ++j) {
            const int col = colBase + wCol + j * 8 + (lane & 3) * 2;
#pragma unroll
            for (int h = 0; h < 2; ++h) {
                const int rr = row + h * 8;
                if (rr < M) {
                    float v0 = acc[i][j][h * 2 + 0];
                    float v1 = acc[i][j][h * 2 + 1];
                    if (bias) {
                        if (col     < Nc) v0 += __ldg(bias + col);
                        if (col + 1 < Nc) v1 += __ldg(bias + col + 1);
                    }
                    if (col     < Nc) Cf[(size_t)rr * Nc + col]     = v0;
                    if (col + 1 < Nc) Cf[(size_t)rr * Nc + col + 1] = v1;
                }
            }
        }
    }
}

// ---------------- fp8 cross-term GEMM: out = Cmain + 2^-11*(A8*B8L + A8L*B8) -
// omode 0: fp32 to Cf.  omode 1: bf16-hi to Ohi + e4m3(v) to O8 + e4m3(lo*2048)
// to O8l (for next layer's operands).  relu applied after the sum.
__global__ __launch_bounds__(128, 2)
void gemm_cross(const unsigned char* __restrict__ A8, const unsigned char* __restrict__ A8L,
                const unsigned char* __restrict__ B8, const unsigned char* __restrict__ B8L,
                const float* __restrict__ Cmain,
                float* __restrict__ Cf, unsigned short* __restrict__ Ohi,
                unsigned char* __restrict__ O8, unsigned char* __restrict__ O8l,
                int M, int Nc, int Kd, int relu, int omode)
{
    const int bx = blockIdx.x, by = blockIdx.y;
    extern __shared__ char smem[];
    const uint32_t sb = smem_to_u32(smem);
    const int tid = threadIdx.x;
    const int lane = tid & 31;
    const int wid = tid >> 5;
    const int wm = wid & 1;
    const int wn = wid >> 1;
    const int wRow = wm * 64, wCol = wn * 64;

    const int rowBase = by * 128;
    const int colBase = bx * 128;
    const int kcount = Kd / 128;
    const int nchunk = 2 * kcount;

    float acc[4][8][4];
#pragma unroll
    for (int i = 0; i < 4; ++i)
#pragma unroll
        for (int j = 0; j < 8; ++j)
#pragma unroll
            for (int q = 0; q < 4; ++q) acc[i][j][q] = 0.f;

    auto load_chunk = [&](int c) {
        const int pass = c / kcount;
        const int k0 = (c % kcount) * 128;
        const unsigned char* As = pass ? A8L : A8;
        const unsigned char* Bs = pass ? B8  : B8L;
        const uint32_t base = sb + (uint32_t)(c & 1) * 32768u;
#pragma unroll
        for (int i = 0; i < 8; ++i) {
            const int u = tid + i * 128;
            const int r = u >> 3, ku = u & 7;
            const int grow = rowBase + r;
            cp_async16(base + (uint32_t)(r * 8 + (ku ^ (r & 7))) * 16,
                       As + (size_t)grow * Kd + k0 + ku * 16, grow < M);
        }
#pragma unroll
        for (int i = 0; i < 8; ++i) {
            const int u = tid + i * 128;
            const int r = u >> 3, ku = u & 7;
            const int grow = colBase + r;
            cp_async16(base + 16384u + (uint32_t)(r * 8 + (ku ^ (r & 7))) * 16,
                       Bs + (size_t)grow * Kd + k0 + ku * 16, grow < Nc);
        }
        cp_commit();
    };

    load_chunk(0);

    for (int c = 0; c < nchunk; ++c) {
        if (c + 1 < nchunk) { load_chunk(c + 1); cp_wait<1>(); }
        else                { cp_wait<0>(); }
        __syncthreads();

        const uint32_t base = sb + (uint32_t)(c & 1) * 32768u;
#pragma unroll
        for (int s = 0; s < 4; ++s) {
            uint32_t a[4][4];
#pragma unroll
            for (int i = 0; i < 4; ++i) {
                const int r = wRow + i * 16 + (lane & 15);
                const int ku = s * 2 + (lane >> 4);
                ldm_x4(a[i], base + (uint32_t)(r * 8 + (ku ^ (r & 7))) * 16);
            }
            uint32_t bf[4][4];
#pragma unroll
            for (int j = 0; j < 4; ++j) {
                const int rn = wCol + j * 16 + (lane & 7) + ((lane >> 4) << 3);
                const int ku = s * 2 + ((lane >> 3) & 1);
                ldm_x4(bf[j], base + 16384u + (uint32_t)(rn * 8 + (ku ^ (rn & 7))) * 16);
            }
#pragma unroll
            for (int i = 0; i < 4; ++i)
#pragma unroll
                for (int j = 0; j < 4; ++j) {
                    mma16832_fp8(acc[i][j * 2 + 0], a[i], bf[j][0], bf[j][1]);
                    mma16832_fp8(acc[i][j * 2 + 1], a[i], bf[j][2], bf[j][3]);
                }
        }
        __syncthreads();
    }

#pragma unroll
    for (int i = 0; i < 4; ++i) {
        const int row = rowBase + wRow + i * 16 + (lane >> 2);
#pragma unroll
        for (int j = 0; j < 8; ++j) {
            const int col = colBase + wCol + j * 8 + (lane & 3) * 2;
#pragma unroll
            for (int h = 0; h < 2; ++h) {
                const int rr = row + h * 8;
                if (rr < M) {
#pragma unroll
                    for (int e = 0; e < 2; ++e) {
                        const int cc = col + e;
                        if (cc < Nc) {
                            float v = Cmain[(size_t)rr * Nc + cc]
                                    + acc[i][j][h * 2 + e] * INV_LO_SCALE;
                            if (relu) v = fmaxf(v, 0.f);
                            if (omode == 0) {
                                Cf[(size_t)rr * Nc + cc] = v;
                            } else {
                                __nv_bfloat16 hb = __float2bfloat16(v);
                                Ohi[(size_t)rr * Nc + cc] = *(unsigned short*)&hb;
                                float lo = v - __bfloat162float(hb);
                                O8 [(size_t)rr * Nc + cc] = to_e4m3(v);
                                O8l[(size_t)rr * Nc + cc] = to_e4m3(lo * LO_SCALE);
                            }
                        }
                    }
                }
            }
        }
    }
}

// ---------------- row L2 normalize (fp32 + fp8 copy) -------------------------
__global__ void normalize_kernel(const float* __restrict__ x) {
    int i = blockIdx.x;
    int tid = threadIdx.x;
    const float* xi = x + (size_t)i * DIM;
    float s = 0.f;
    for (int d = tid; d < DIM; d += 256) { float v = xi[d]; s += v * v; }
    __shared__ float sh[256];
    sh[tid] = s; __syncthreads();
    for (int o = 128; o > 0; o >>= 1) {
        if (tid < o) sh[tid] += sh[tid + o];
        __syncthreads();
    }
    float inv = 1.f / fmaxf(sqrtf(sh[0]), 1e-12f);
    float* out = g_xn + (size_t)i * DIM;
    unsigned char* out8 = g_x8 + (size_t)i * DIM;
    for (int d = tid; d < DIM; d += 256) {
        float v = xi[d] * inv;
        out[d] = v;
        out8[d] = to_e4m3(v * FP8_SCALE);
    }
}

// ---------------- weight split: bf16 hi + e4m3(v) + e4m3(lo*2048) ------------
__global__ void split_w_kernel(const float* __restrict__ src,
                               unsigned short* __restrict__ hi,
                               unsigned char* __restrict__ f8,
                               unsigned char* __restrict__ f8l, size_t n) {
    size_t i = (size_t)blockIdx.x * 256 + threadIdx.x;
    if (i >= n) return;
    float v = src[i];
    __nv_bfloat16 h = __float2bfloat16(v);
    hi[i] = *(unsigned short*)&h;
    f8[i] = to_e4m3(v);
    f8l[i] = to_e4m3((v - __bfloat162float(h)) * LO_SCALE);
}

// ---------------- radix-select exact per-row top-16 (bf16 sims) --------------
#define TK_THREADS 256
#define TK_BUF 1024

__global__ __launch_bounds__(TK_THREADS)
void topk_kernel() {
    const int i = blockIdx.x;
    const int tid = threadIdx.x;
    const int wid = tid >> 5, lane = tid & 31;
    const uint4* row4 = (const uint4*)(g_sim + (size_t)i * N_PTS);

    __shared__ int hist[8 * 264];
    __shared__ int hist2[256];
    __shared__ uint32_t buf[TK_BUF];
    __shared__ int nbuf;
    __shared__ int s_b, s_cntAbove;
    __shared__ uint32_t s_T;

    for (int b = tid; b < 8 * 264; b += TK_THREADS) hist[b] = 0;
    for (int b = tid; b < 256; b += TK_THREADS) hist2[b] = 0;
    if (tid == 0) nbuf = 0;
    __syncthreads();

    int* myh = hist + wid * 264;
    for (int j16 = tid; j16 < N_PTS / 8; j16 += TK_THREADS) {
        uint4 u = row4[j16];
        uint32_t w[4] = {u.x, u.y, u.z, u.w};
#pragma unroll
        for (int q = 0; q < 4; ++q) {
#pragma unroll
            for (int e = 0; e < 2; ++e) {
                uint32_t k = sortable16((w[q] >> (e * 16)) & 0xFFFFu);
                atomicAdd(&myh[k >> 8], 1);
            }
        }
    }
    __syncthreads();
    for (int b = tid; b < 256; b += TK_THREADS) {
        int s = 0;
#pragma unroll
        for (int w = 0; w < 8; ++w) s += hist[w * 264 + b];
        hist[b] = s;
    }
    __syncthreads();
    if (tid == 0) {
        int cum = 0, b = 255;
        for (; b > 0; --b) {
            if (cum + hist[b] >= CAND) break;
            cum += hist[b];
        }
        s_b = b; s_cntAbove = cum;
    }
    __syncthreads();
    const uint32_t bstar = (uint32_t)s_b;

    for (int j16 = tid; j16 < N_PTS / 8; j16 += TK_THREADS) {
        uint4 u = row4[j16];
        uint32_t w[4] = {u.x, u.y, u.z, u.w};
#pragma unroll
        for (int q = 0; q < 4; ++q) {
#pragma unroll
            for (int e = 0; e < 2; ++e) {
                uint32_t k = sortable16((w[q] >> (e * 16)) & 0xFFFFu);
                if ((k >> 8) == bstar) atomicAdd(&hist2[k & 0xFFu], 1);
            }
        }
    }
    __syncthreads();
    if (tid == 0) {
        int cum = s_cntAbove, s = 255;
        for (; s > 0; --s) {
            if (cum + hist2[s] >= CAND) break;
            cum += hist2[s];
        }
        s_T = (bstar << 8) | (uint32_t)s;
    }
    __syncthreads();
    const uint32_t T = s_T;

    for (int j16 = tid; j16 < N_PTS / 8; j16 += TK_THREADS) {
        uint4 u = row4[j16];
        uint32_t w[4] = {u.x, u.y, u.z, u.w};
#pragma unroll
        for (int q = 0; q < 4; ++q) {
#pragma unroll
            for (int e = 0; e < 2; ++e) {
                uint32_t k = sortable16((w[q] >> (e * 16)) & 0xFFFFu);
                if (k >= T) {
                    int p = atomicAdd(&nbuf, 1);
                    if (p < TK_BUF) {
                        int j = j16 * 8 + q * 2 + e;
                        buf[p] = (k << 16) | (uint32_t)(8191 - j);
                    }
                }
            }
        }
    }
    __syncthreads();

    if (wid == 0) {
        int count = min(nbuf, TK_BUF);
        for (int r = 0; r < CAND; ++r) {
            uint32_t best = 0; int bp = -1;
            for (int p = lane; p < count; p += 32)
                if (buf[p] > best) { best = buf[p]; bp = p; }
#pragma unroll
            for (int o = 16; o > 0; o >>= 1) {
                uint32_t ob = __shfl_xor_sync(0xffffffffu, best, o);
                int      op = __shfl_xor_sync(0xffffffffu, bp, o);
                if (ob > best) { best = ob; bp = op; }
            }
            if (lane == 0) {
                g_cand[(size_t)i * CAND + r] = 8191 - (int)(best & 0xFFFFu);
                buf[bp] = 0;
            }
            __syncwarp();
        }
    }
}

// ---------------- exact fp32 rescore of 16 candidates -> top-6 ---------------
__device__ __forceinline__ bool better(float v1, int i1, float v2, int i2) {
    return (v1 > v2) || (v1 == v2 && i1 < i2);
}

__global__ void rescore_kernel() {
    int i = blockIdx.x;
    int tid = threadIdx.x;
    int wid = tid >> 5, lane = tid & 31;
    __shared__ float xi[DIM];
    __shared__ int cand[CAND];
    __shared__ float red[CAND][8];
    for (int d = tid; d < DIM; d += 256) xi[d] = g_xn[(size_t)i * DIM + d];
    if (tid < CAND) cand[tid] = g_cand[(size_t)i * CAND + tid];
    __syncthreads();

    float acc[CAND];
#pragma unroll
    for (int c = 0; c < CAND; ++c) acc[c] = 0.f;
    for (int d = tid; d < DIM; d += 256) {
        float xv = xi[d];
#pragma unroll
        for (int c = 0; c < CAND; ++c)
            acc[c] += xv * g_xn[(size_t)cand[c] * DIM + d];
    }
#pragma unroll
    for (int c = 0; c < CAND; ++c) {
#pragma unroll
        for (int o = 16; o > 0; o >>= 1)
            acc[c] += __shfl_xor_sync(0xffffffffu, acc[c], o);
        if (lane == 0) red[c][wid] = acc[c];
    }
    __syncthreads();
    if (tid == 0) {
        float cv[CAND]; int ci[CAND];
#pragma unroll
        for (int c = 0; c < CAND; ++c) {
            float s = 0.f;
#pragma unroll
            for (int w = 0; w < 8; ++w) s += red[c][w];
            cv[c] = s; ci[c] = cand[c];
        }
        for (int r = 0; r < KNN; ++r) {
            int bp = r;
            for (int c = r + 1; c < CAND; ++c)
                if (better(cv[c], ci[c], cv[bp], ci[bp])) bp = c;
            float tv = cv[r]; cv[r] = cv[bp]; cv[bp] = tv;
            int   ti = ci[r]; ci[r] = ci[bp]; ci[bp] = ti;
            g_idx[(size_t)i * KNN + r] = ci[r];
        }
    }
}

// ---------------- k-reciprocal + GIN aggregation -> h0 operands --------------
__global__ void aggr_kernel(const float* __restrict__ x) {
    int i = blockIdx.x;
    int tid = threadIdx.x;
    __shared__ int nb[KNN];
    __shared__ int ok[KNN];
    if (tid < KNN) {
        int j = g_idx[(size_t)i * KNN + tid];
        nb[tid] = j;
        int r = 0;
#pragma unroll
        for (int t = 0; t < KNN; ++t) r |= (g_idx[(size_t)j * KNN + t] == i);
        ok[tid] = r;
    }
    __syncthreads();
    for (int d = tid; d < DIM; d += 256) {
        float acc = GIN_ONE_PLUS_EPS * x[(size_t)i * DIM + d];
#pragma unroll
        for (int c = 0; c < KNN; ++c)
            if (ok[c]) acc += x[(size_t)nb[c] * DIM + d];
        __nv_bfloat16 h = __float2bfloat16(acc);
        size_t idx = (size_t)i * DIM + d;
        g_sh[idx] = *(unsigned short*)&h;
        g_a8[idx] = to_e4m3(acc);
        g_a8l[idx] = to_e4m3((acc - __bfloat162float(h)) * LO_SCALE);
    }
}

// ---------------- BatchNorm (training-mode batch stats) ----------------------
__global__ void bn_zero_kernel() {
    int c = blockIdx.x * 256 + threadIdx.x;
    if (c < DIM) { g_scale[c] = 0.f; g_shift[c] = 0.f; }
}

__global__ void bn_stats_kernel() {
    int c  = blockIdx.x * 256 + threadIdx.x;
    int r0 = blockIdx.y * 256;
    float s = 0.f, q = 0.f;
    for (int r = r0; r < r0 + 256; ++r) {
        float v = g_h2[(size_t)r * DIM + c];
        s += v; q += v * v;
    }
    atomicAdd(&g_scale[c], s);
    atomicAdd(&g_shift[c], q);
}

__global__ void bn_finalize_kernel(const float* __restrict__ gamma,
                                   const float* __restrict__ beta) {
    int c = blockIdx.x * 256 + threadIdx.x;
    if (c >= DIM) return;
    const float invN = 1.f / (float)N_PTS;
    float mean = g_scale[c] * invN;
    float var  = g_shift[c] * invN - mean * mean;
    float sc   = gamma[c] * rsqrtf(var + BN_EPS);
    g_scale[c] = sc;
    g_shift[c] = beta[c] - mean * sc;
}

__global__ void bn_apply_kernel() {
    size_t idx = (size_t)blockIdx.x * 256 + threadIdx.x;
    int c = (int)(idx & (DIM - 1));
    float v = g_h2[idx] * g_scale[c] + g_shift[c];
    __nv_bfloat16 h = __float2bfloat16(v);
    g_sh[idx] = *(unsigned short*)&h;
    g_a8[idx] = to_e4m3(v);
    g_a8l[idx] = to_e4m3((v - __bfloat162float(h)) * LO_SCALE);
}

// ---------------- launch -----------------------------------------------------
extern "C" void kernel_launch(void* const* d_in, const int* in_sizes, int n_in,
                              void* d_out, int out_size) {
    const float* x     = (const float*)d_in[0];
    const float* w1    = (const float*)d_in[1];
    const float* b1    = (const float*)d_in[2];
    const float* w2    = (const float*)d_in[3];
    const float* b2    = (const float*)d_in[4];
    const float* gamma = (const float*)d_in[5];
    const float* beta  = (const float*)d_in[6];
    const float* wc    = (const float*)d_in[7];
    float* out = (float*)d_out;

    cudaFuncSetAttribute(gemm_main, cudaFuncAttributeMaxDynamicSharedMemorySize, SMEM_GEMM);
    cudaFuncSetAttribute(gemm_cross, cudaFuncAttributeMaxDynamicSharedMemorySize, SMEM_GEMM);
    cudaFuncSetAttribute(sim_fp8,  cudaFuncAttributeMaxDynamicSharedMemorySize, SMEM_GEMM);

    float *p_xn, *p_h2;
    unsigned char *p_x8, *p_a8, *p_a8l, *p_b8, *p_b8l;
    unsigned char *p_w18, *p_w18l, *p_w28, *p_w28l, *p_wc8, *p_wc8l;
    unsigned short *p_sim, *p_sh, *p_th, *p_w1h, *p_w2h, *p_wch;
    cudaGetSymbolAddress((void**)&p_xn,  g_xn);
    cudaGetSymbolAddress((void**)&p_x8,  g_x8);
    cudaGetSymbolAddress((void**)&p_sim, g_sim);
    cudaGetSymbolAddress((void**)&p_h2,  g_h2);
    cudaGetSymbolAddress((void**)&p_sh,  g_sh);
    cudaGetSymbolAddress((void**)&p_th,  g_th);
    cudaGetSymbolAddress((void**)&p_a8,  g_a8);
    cudaGetSymbolAddress((void**)&p_a8l, g_a8l);
    cudaGetSymbolAddress((void**)&p_b8,  g_b8);
    cudaGetSymbolAddress((void**)&p_b8l, g_b8l);
    cudaGetSymbolAddress((void**)&p_w1h, g_w1h);
    cudaGetSymbolAddress((void**)&p_w2h, g_w2h);
    cudaGetSymbolAddress((void**)&p_wch, g_wch);
    cudaGetSymbolAddress((void**)&p_w18, g_w18);
    cudaGetSymbolAddress((void**)&p_w18l, g_w18l);
    cudaGetSymbolAddress((void**)&p_w28, g_w28);
    cudaGetSymbolAddress((void**)&p_w28l, g_w28l);
    cudaGetSymbolAddress((void**)&p_wc8, g_wc8);
    cudaGetSymbolAddress((void**)&p_wc8l, g_wc8l);

    float* p_ctmp = (float*)p_sim;     // 64 MB fp32 temp (g_sim free after topk)

    const size_t nDD = (size_t)DIM * DIM;
    const size_t nCD = (size_t)NCLS * DIM;
    const size_t nND = (size_t)N_PTS * DIM;

    normalize_kernel<<<N_PTS, 256>>>(x);
    split_w_kernel<<<(unsigned)((nDD + 255) / 256), 256>>>(w1, p_w1h, p_w18, p_w18l, nDD);
    split_w_kernel<<<(unsigned)((nDD + 255) / 256), 256>>>(w2, p_w2h, p_w28, p_w28l, nDD);

    // similarity (fp8 e4m3 HMMA, symmetric, bf16 raw-scale sims)
    sim_fp8<<<dim3(64, 64), 128, SMEM_GEMM>>>(p_x8, p_sim);

    split_w_kernel<<<(unsigned)((nCD + 255) / 256), 256>>>(wc, p_wch, p_wc8, p_wc8l, nCD);

    // radix-select top-16 candidates, exact fp32 rescore -> top-6
    topk_kernel<<<N_PTS, TK_THREADS>>>();
    rescore_kernel<<<N_PTS, 256>>>();

    // k-reciprocal + GIN aggregation -> h0 operands (bf16 hi + fp8 pair)
    aggr_kernel<<<N_PTS, 256>>>(x);

    // MLP layer 1: main bf16 pass + fp8 cross pass (relu, split outputs)
    gemm_main<<<dim3(16, 64), 128, SMEM_GEMM>>>(
        (const __nv_bfloat16*)p_sh, (const __nv_bfloat16*)p_w1h,
        p_ctmp, N_PTS, DIM, DIM, b1);
    gemm_cross<<<dim3(16, 64), 128, SMEM_GEMM>>>(
        p_a8, p_a8l, p_w18, p_w18l, p_ctmp,
        nullptr, p_th, p_b8, p_b8l, N_PTS, DIM, DIM, 1, 1);

    // MLP layer 2: main + cross -> h2 fp32
    gemm_main<<<dim3(16, 64), 128, SMEM_GEMM>>>(
        (const __nv_bfloat16*)p_th, (const __nv_bfloat16*)p_w2h,
        p_ctmp, N_PTS, DIM, DIM, b2);
    gemm_cross<<<dim3(16, 64), 128, SMEM_GEMM>>>(
        p_b8, p_b8l, p_w28, p_w28l, p_ctmp,
        p_h2, nullptr, nullptr, nullptr, N_PTS, DIM, DIM, 0, 0);

    // BatchNorm -> hn operands
    bn_zero_kernel<<<(DIM + 255) / 256, 256>>>();
    bn_stats_kernel<<<dim3(DIM / 256, N_PTS / 256), 256>>>();
    bn_finalize_kernel<<<(DIM + 255) / 256, 256>>>(gamma, beta);
    bn_apply_kernel<<<(unsigned)(nND / 256), 256>>>();

    // classifier: main + cross -> out [8192, 751]
    gemm_main<<<dim3((NCLS + 127) / 128, 64), 128, SMEM_GEMM>>>(
        (const __nv_bfloat16*)p_sh, (const __nv_bfloat16*)p_wch,
        p_ctmp, N_PTS, NCLS, DIM, nullptr);
    gemm_cross<<<dim3((NCLS + 127) / 128, 64), 128, SMEM_GEMM>>>(
        p_a8, p_a8l, p_wc8, p_wc8l, p_ctmp,
        out, nullptr, nullptr, nullptr, N_PTS, NCLS, DIM, 0, 0);
}

// round 13
// speedup vs baseline: 1.0249x; 1.0249x over previous
#include <cuda_runtime.h>
#include <cuda_bf16.h>
#include <cuda_fp8.h>
#include <cstdint>
#include <math.h>

#define N_PTS 8192
#define DIM   2048
#define NCLS  751
#define KNN   6
#define CAND  16
#define GIN_ONE_PLUS_EPS 1.3f
#define BN_EPS 1e-5f
#define FP8_SCALE 256.0f

// ---------------- scratch ----------------------------------------------------
__device__ float g_xn [(size_t)N_PTS * DIM];
__device__ unsigned char g_x8 [(size_t)N_PTS * DIM];      // e4m3 of xn*256
__device__ unsigned short g_sim[(size_t)N_PTS * N_PTS];   // bf16 sims (raw scale)
__device__ int   g_cand[(size_t)N_PTS * CAND];
__device__ int   g_idx[(size_t)N_PTS * KNN];
__device__ float g_h2 [(size_t)N_PTS * DIM];
__device__ unsigned short g_sh [(size_t)N_PTS * DIM];     // act split hi (h0, later hn)
__device__ unsigned short g_sl [(size_t)N_PTS * DIM];     // act split lo
__device__ unsigned short g_th [(size_t)N_PTS * DIM];     // h1 split hi
__device__ unsigned short g_tl [(size_t)N_PTS * DIM];     // h1 split lo
__device__ unsigned short g_w1h[(size_t)DIM * DIM], g_w1l[(size_t)DIM * DIM];
__device__ unsigned short g_w2h[(size_t)DIM * DIM], g_w2l[(size_t)DIM * DIM];
__device__ unsigned short g_wch[(size_t)NCLS * DIM], g_wcl[(size_t)NCLS * DIM];
__device__ float g_scale[DIM];
__device__ float g_shift[DIM];

// ---------------- helpers ----------------------------------------------------
__device__ __forceinline__ uint32_t smem_to_u32(const void* p) {
    uint32_t a;
    asm("{ .reg .u64 t; cvta.to.shared.u64 t, %1; cvt.u32.u64 %0, t; }" : "=r"(a) : "l"(p));
    return a;
}

__device__ __forceinline__ void cp_async16(uint32_t dst, const void* src, int valid) {
    asm volatile("cp.async.cg.shared.global [%0], [%1], 16, %2;"
                 :: "r"(dst), "l"(src), "r"(valid ? 16 : 0) : "memory");
}
__device__ __forceinline__ void cp_commit() {
    asm volatile("cp.async.commit_group;" ::: "memory");
}
template <int N>
__device__ __forceinline__ void cp_wait() {
    asm volatile("cp.async.wait_group %0;" :: "n"(N) : "memory");
}

__device__ __forceinline__ void ldm_x4(uint32_t* r, uint32_t addr) {
    asm volatile("ldmatrix.sync.aligned.m8n8.x4.shared.b16 {%0,%1,%2,%3}, [%4];"
                 : "=r"(r[0]), "=r"(r[1]), "=r"(r[2]), "=r"(r[3]) : "r"(addr));
}

__device__ __forceinline__ void mma16816(float* d, const uint32_t* a, uint32_t b0, uint32_t b1) {
    asm volatile("mma.sync.aligned.m16n8k16.row.col.f32.bf16.bf16.f32 "
                 "{%0,%1,%2,%3}, {%4,%5,%6,%7}, {%8,%9}, {%0,%1,%2,%3};"
                 : "+f"(d[0]), "+f"(d[1]), "+f"(d[2]), "+f"(d[3])
                 : "r"(a[0]), "r"(a[1]), "r"(a[2]), "r"(a[3]), "r"(b0), "r"(b1));
}

__device__ __forceinline__ void mma16832_fp8(float* d, const uint32_t* a, uint32_t b0, uint32_t b1) {
    asm volatile("mma.sync.aligned.m16n8k32.row.col.f32.e4m3.e4m3.f32 "
                 "{%0,%1,%2,%3}, {%4,%5,%6,%7}, {%8,%9}, {%0,%1,%2,%3};"
                 : "+f"(d[0]), "+f"(d[1]), "+f"(d[2]), "+f"(d[3])
                 : "r"(a[0]), "r"(a[1]), "r"(a[2]), "r"(a[3]), "r"(b0), "r"(b1));
}

__device__ __forceinline__ uint32_t pack_split_hi(float v0, float v1, uint32_t& lo_pack) {
    __nv_bfloat16 h0 = __float2bfloat16(v0);
    __nv_bfloat16 h1 = __float2bfloat16(v1);
    __nv_bfloat16 l0 = __float2bfloat16(v0 - __bfloat162float(h0));
    __nv_bfloat16 l1 = __float2bfloat16(v1 - __bfloat162float(h1));
    unsigned short uh0 = *(unsigned short*)&h0, uh1 = *(unsigned short*)&h1;
    unsigned short ul0 = *(unsigned short*)&l0, ul1 = *(unsigned short*)&l1;
    lo_pack = (uint32_t)ul0 | ((uint32_t)ul1 << 16);
    return (uint32_t)uh0 | ((uint32_t)uh1 << 16);
}

// bf16 bit pattern -> order-preserving 16-bit key (bigger = larger value)
__device__ __forceinline__ uint32_t sortable16(uint32_t us) {
    return (us & 0x8000u) ? (~us & 0xFFFFu) : (us | 0x8000u);
}

#define SMEM_GEMM 66048   // max(2*32768 pipeline, 128*129*4 transpose stage)

// ---------------- fp8 similarity GEMM: C = X*X^T (bf16 out, raw scale) -------
// 128x128 CTA tile, BK=128 fp8 bytes, 256 thr (8 warps 2x4, warp tile 32x64),
// cp.async double buffer, swizzled smem, 2 CTAs/SM (16 warps: latency cover
// for the 2x-rate fp8 MMA pipe). Symmetric: bx<=by computed, mirror via smem.
__global__ __launch_bounds__(256, 2)
void sim_fp8(const unsigned char* __restrict__ X, unsigned short* __restrict__ C)
{
    const int bx = blockIdx.x, by = blockIdx.y;
    if (bx > by) return;

    extern __shared__ char smem[];
    const uint32_t sb = smem_to_u32(smem);
    const int tid = threadIdx.x;
    const int lane = tid & 31;
    const int wid = tid >> 5;
    const int wm = wid & 3;          // 0..3 (M dir, 32 rows each)
    const int wn = wid >> 2;         // 0..1 (N dir, 64 cols each)
    const int wRow = wm * 32, wCol = wn * 64;

    const int rowBase = by * 128;
    const int colBase = bx * 128;
    const int nchunk = DIM / 128;          // 16

    float acc[2][8][4];
#pragma unroll
    for (int i = 0; i < 2; ++i)
#pragma unroll
        for (int j = 0; j < 8; ++j)
#pragma unroll
            for (int q = 0; q < 4; ++q) acc[i][j][q] = 0.f;

    auto load_chunk = [&](int c) {
        const int k0 = c * 128;
        const uint32_t base = sb + (uint32_t)(c & 1) * 32768u;
#pragma unroll
        for (int i = 0; i < 4; ++i) {      // A tile: 128 rows x 128B
            const int u = tid + i * 256;
            const int r = u >> 3, ku = u & 7;
            cp_async16(base + (uint32_t)(r * 8 + (ku ^ (r & 7))) * 16,
                       X + (size_t)(rowBase + r) * DIM + k0 + ku * 16, 1);
        }
#pragma unroll
        for (int i = 0; i < 4; ++i) {      // B tile
            const int u = tid + i * 256;
            const int r = u >> 3, ku = u & 7;
            cp_async16(base + 16384u + (uint32_t)(r * 8 + (ku ^ (r & 7))) * 16,
                       X + (size_t)(colBase + r) * DIM + k0 + ku * 16, 1);
        }
        cp_commit();
    };

    load_chunk(0);

    for (int c = 0; c < nchunk; ++c) {
        if (c + 1 < nchunk) { load_chunk(c + 1); cp_wait<1>(); }
        else                { cp_wait<0>(); }
        __syncthreads();

        const uint32_t base = sb + (uint32_t)(c & 1) * 32768u;
#pragma unroll
        for (int s = 0; s < 4; ++s) {      // four k32 steps (32B each)
            uint32_t a[2][4];
#pragma unroll
            for (int i = 0; i < 2; ++i) {
                const int r = wRow + i * 16 + (lane & 15);
                const int ku = s * 2 + (lane >> 4);
                ldm_x4(a[i], base + (uint32_t)(r * 8 + (ku ^ (r & 7))) * 16);
            }
            uint32_t bf[4][4];
#pragma unroll
            for (int j = 0; j < 4; ++j) {
                const int rn = wCol + j * 16 + (lane & 7) + ((lane >> 4) << 3);
                const int ku = s * 2 + ((lane >> 3) & 1);
                ldm_x4(bf[j], base + 16384u + (uint32_t)(rn * 8 + (ku ^ (rn & 7))) * 16);
            }
#pragma unroll
            for (int i = 0; i < 2; ++i)
#pragma unroll
                for (int j = 0; j < 4; ++j) {
                    mma16832_fp8(acc[i][j * 2 + 0], a[i], bf[j][0], bf[j][1]);
                    mma16832_fp8(acc[i][j * 2 + 1], a[i], bf[j][2], bf[j][3]);
                }
        }
        __syncthreads();
    }

    // ---- epilogue: bf16 pair stores ----
#pragma unroll
    for (int i = 0; i < 2; ++i) {
        const int row = rowBase + wRow + i * 16 + (lane >> 2);
#pragma unroll
        for (int j = 0; j < 8; ++j) {
            const int col = colBase + wCol + j * 8 + (lane & 3) * 2;
#pragma unroll
            for (int h = 0; h < 2; ++h) {
                const int rr = row + h * 8;
                __nv_bfloat16 b0 = __float2bfloat16(acc[i][j][h * 2 + 0]);
                __nv_bfloat16 b1 = __float2bfloat16(acc[i][j][h * 2 + 1]);
                uint32_t pk = (uint32_t)(*(unsigned short*)&b0) |
                              ((uint32_t)(*(unsigned short*)&b1) << 16);
                *(uint32_t*)(C + (size_t)rr * N_PTS + col) = pk;
            }
        }
    }

    // ---- mirror tile (coalesced per-cc row writes, both thread halves) ----
    if (bx < by) {
        __syncthreads();
        float* sc = (float*)smem;          // [128][129]
#pragma unroll
        for (int i = 0; i < 2; ++i) {
            const int lr = wRow + i * 16 + (lane >> 2);
#pragma unroll
            for (int j = 0; j < 8; ++j) {
                const int lc = wCol + j * 8 + (lane & 3) * 2;
                sc[(lr    ) * 129 + lc    ] = acc[i][j][0];
                sc[(lr    ) * 129 + lc + 1] = acc[i][j][1];
                sc[(lr + 8) * 129 + lc    ] = acc[i][j][2];
                sc[(lr + 8) * 129 + lc + 1] = acc[i][j][3];
            }
        }
        __syncthreads();
        const int half = tid >> 7;         // 0 or 1
        const int t    = tid & 127;
        for (int cc = half; cc < 128; cc += 2) {
            __nv_bfloat16 b = __float2bfloat16(sc[t * 129 + cc]);
            C[(size_t)(colBase + cc) * N_PTS + rowBase + t] = *(unsigned short*)&b;
        }
    }
}

// ---------------- bf16 mma.sync GEMM: C[M,Nc] = A[M,K] * B[Nc,K]^T ----------
// 128x128 CTA tile, BK=64, 128 thr (4 warps 2x2, warp tile 64x64), 2 CTAs/SM.
// three=1: acc = Ah*Bh + Ah*Bl + Al*Bh (hi/lo bf16 split, fp32 accum).
__global__ __launch_bounds__(128, 2)
void gemm_mma(const __nv_bfloat16* __restrict__ Ah, const __nv_bfloat16* __restrict__ Al,
              const __nv_bfloat16* __restrict__ Bh, const __nv_bfloat16* __restrict__ Bl,
              float* __restrict__ Cf,
              unsigned short* __restrict__ Chi, unsigned short* __restrict__ Clo,
              int M, int Nc, int Kd,
              const float* __restrict__ bias, int relu, int omode)
{
    const int bx = blockIdx.x, by = blockIdx.y;
    extern __shared__ char smem[];
    const uint32_t sb = smem_to_u32(smem);
    const int tid = threadIdx.x;
    const int lane = tid & 31;
    const int wid = tid >> 5;
    const int wm = wid & 1;
    const int wn = wid >> 1;
    const int wRow = wm * 64, wCol = wn * 64;

    const int rowBase = by * 128;
    const int colBase = bx * 128;
    const int kcount = Kd / 64;
    const int nchunk = 3 * kcount;

    float acc[4][8][4];
#pragma unroll
    for (int i = 0; i < 4; ++i)
#pragma unroll
        for (int j = 0; j < 8; ++j)
#pragma unroll
            for (int q = 0; q < 4; ++q) acc[i][j][q] = 0.f;

    auto load_chunk = [&](int c) {
        const int pass = c / kcount;
        const int k0 = (c % kcount) * 64;
        const __nv_bfloat16* As = (pass == 2) ? Al : Ah;
        const __nv_bfloat16* Bs = (pass == 1) ? Bl : Bh;
        const uint32_t base = sb + (uint32_t)(c & 1) * 32768u;
#pragma unroll
        for (int i = 0; i < 8; ++i) {
            const int u = tid + i * 128;
            const int r = u >> 3, ku = u & 7;
            const int grow = rowBase + r;
            cp_async16(base + (uint32_t)(r * 8 + (ku ^ (r & 7))) * 16,
                       As + (size_t)grow * Kd + k0 + ku * 8, grow < M);
        }
#pragma unroll
        for (int i = 0; i < 8; ++i) {
            const int u = tid + i * 128;
            const int r = u >> 3, ku = u & 7;
            const int grow = colBase + r;
            cp_async16(base + 16384u + (uint32_t)(r * 8 + (ku ^ (r & 7))) * 16,
                       Bs + (size_t)grow * Kd + k0 + ku * 8, grow < Nc);
        }
        cp_commit();
    };

    load_chunk(0);

    for (int c = 0; c < nchunk; ++c) {
        if (c + 1 < nchunk) { load_chunk(c + 1); cp_wait<1>(); }
        else                { cp_wait<0>(); }
        __syncthreads();

        const uint32_t base = sb + (uint32_t)(c & 1) * 32768u;
#pragma unroll
        for (int s = 0; s < 4; ++s) {
            uint32_t a[4][4];
#pragma unroll
            for (int i = 0; i < 4; ++i) {
                const int r = wRow + i * 16 + (lane & 15);
                const int ku = s * 2 + (lane >> 4);
                ldm_x4(a[i], base + (uint32_t)(r * 8 + (ku ^ (r & 7))) * 16);
            }
            uint32_t bf[4][4];
#pragma unroll
            for (int j = 0; j < 4; ++j) {
                const int rn = wCol + j * 16 + (lane & 7) + ((lane >> 4) << 3);
                const int ku = s * 2 + ((lane >> 3) & 1);
                ldm_x4(bf[j], base + 16384u + (uint32_t)(rn * 8 + (ku ^ (rn & 7))) * 16);
            }
#pragma unroll
            for (int i = 0; i < 4; ++i)
#pragma unroll
                for (int j = 0; j < 4; ++j) {
                    mma16816(acc[i][j * 2 + 0], a[i], bf[j][0], bf[j][1]);
                    mma16816(acc[i][j * 2 + 1], a[i], bf[j][2], bf[j][3]);
                }
        }
        __syncthreads();
    }

#pragma unroll
    for (int i = 0; i < 4; ++i) {
        const int row = rowBase + wRow + i * 16 + (lane >> 2);
#pragma unroll
        for (int j = 0; j < 8; ++j) {
            const int col = colBase + wCol + j * 8 + (lane & 3) * 2;
#pragma unroll
            for (int h = 0; h < 2; ++h) {
                const int rr = row + h * 8;
                if (rr < M) {
                    float v0 = acc[i][j][h * 2 + 0];
                    float v1 = acc[i][j][h * 2 + 1];
                    if (bias) {
                        if (col     < Nc) v0 += __ldg(bias + col);
                        if (col + 1 < Nc) v1 += __ldg(bias + col + 1);
                    }
                    if (relu) { v0 = fmaxf(v0, 0.f); v1 = fmaxf(v1, 0.f); }
                    if (omode == 0) {
                        if (col     < Nc) Cf[(size_t)rr * Nc + col]     = v0;
                        if (col + 1 < Nc) Cf[(size_t)rr * Nc + col + 1] = v1;
                    } else if (col + 1 < Nc) {
                        uint32_t lo_pack;
                        uint32_t hi_pack = pack_split_hi(v0, v1, lo_pack);
                        *(uint32_t*)(Chi + (size_t)rr * Nc + col) = hi_pack;
                        *(uint32_t*)(Clo + (size_t)rr * Nc + col) = lo_pack;
                    }
                }
            }
        }
    }
}

// ---------------- row L2 normalize (fp32 + fp8 copy) -------------------------
__global__ void normalize_kernel(const float* __restrict__ x) {
    int i = blockIdx.x;
    int tid = threadIdx.x;
    const float* xi = x + (size_t)i * DIM;
    float s = 0.f;
    for (int d = tid; d < DIM; d += 256) { float v = xi[d]; s += v * v; }
    __shared__ float sh[256];
    sh[tid] = s; __syncthreads();
    for (int o = 128; o > 0; o >>= 1) {
        if (tid < o) sh[tid] += sh[tid + o];
        __syncthreads();
    }
    float inv = 1.f / fmaxf(sqrtf(sh[0]), 1e-12f);
    float* out = g_xn + (size_t)i * DIM;
    unsigned char* out8 = g_x8 + (size_t)i * DIM;
    for (int d = tid; d < DIM; d += 256) {
        float v = xi[d] * inv;
        out[d] = v;
        out8[d] = (unsigned char)__nv_cvt_float_to_fp8(v * FP8_SCALE,
                                                       __NV_SATFINITE, __NV_E4M3);
    }
}

// ---------------- bf16 hi/lo split (weights only) ----------------------------
__global__ void split_kernel(const float* __restrict__ src,
                             unsigned short* __restrict__ hi,
                             unsigned short* __restrict__ lo, size_t n) {
    size_t i = (size_t)blockIdx.x * 256 + threadIdx.x;
    if (i >= n) return;
    float v = src[i];
    __nv_bfloat16 h = __float2bfloat16(v);
    ((__nv_bfloat16*)hi)[i] = h;
    ((__nv_bfloat16*)lo)[i] = __float2bfloat16(v - __bfloat162float(h));
}

// ---------------- radix-select exact per-row top-16 (bf16 sims) --------------
#define TK_THREADS 256
#define TK_BUF 1024

__global__ __launch_bounds__(TK_THREADS)
void topk_kernel() {
    const int i = blockIdx.x;
    const int tid = threadIdx.x;
    const int wid = tid >> 5, lane = tid & 31;
    const uint4* row4 = (const uint4*)(g_sim + (size_t)i * N_PTS);

    __shared__ int hist[8 * 264];
    __shared__ int hist2[256];
    __shared__ uint32_t buf[TK_BUF];
    __shared__ int nbuf;
    __shared__ int s_b, s_cntAbove;
    __shared__ uint32_t s_T;

    for (int b = tid; b < 8 * 264; b += TK_THREADS) hist[b] = 0;
    for (int b = tid; b < 256; b += TK_THREADS) hist2[b] = 0;
    if (tid == 0) nbuf = 0;
    __syncthreads();

    int* myh = hist + wid * 264;
    for (int j16 = tid; j16 < N_PTS / 8; j16 += TK_THREADS) {
        uint4 u = row4[j16];
        uint32_t w[4] = {u.x, u.y, u.z, u.w};
#pragma unroll
        for (int q = 0; q < 4; ++q) {
#pragma unroll
            for (int e = 0; e < 2; ++e) {
                uint32_t k = sortable16((w[q] >> (e * 16)) & 0xFFFFu);
                atomicAdd(&myh[k >> 8], 1);
            }
        }
    }
    __syncthreads();
    for (int b = tid; b < 256; b += TK_THREADS) {
        int s = 0;
#pragma unroll
        for (int w = 0; w < 8; ++w) s += hist[w * 264 + b];
        hist[b] = s;
    }
    __syncthreads();
    if (tid == 0) {
        int cum = 0, b = 255;
        for (; b > 0; --b) {
            if (cum + hist[b] >= CAND) break;
            cum += hist[b];
        }
        s_b = b; s_cntAbove = cum;
    }
    __syncthreads();
    const uint32_t bstar = (uint32_t)s_b;

    for (int j16 = tid; j16 < N_PTS / 8; j16 += TK_THREADS) {
        uint4 u = row4[j16];
        uint32_t w[4] = {u.x, u.y, u.z, u.w};
#pragma unroll
        for (int q = 0; q < 4; ++q) {
#pragma unroll
            for (int e = 0; e < 2; ++e) {
                uint32_t k = sortable16((w[q] >> (e * 16)) & 0xFFFFu);
                if ((k >> 8) == bstar) atomicAdd(&hist2[k & 0xFFu], 1);
            }
        }
    }
    __syncthreads();
    if (tid == 0) {
        int cum = s_cntAbove, s = 255;
        for (; s > 0; --s) {
            if (cum + hist2[s] >= CAND) break;
            cum += hist2[s];
        }
        s_T = (bstar << 8) | (uint32_t)s;
    }
    __syncthreads();
    const uint32_t T = s_T;

    for (int j16 = tid; j16 < N_PTS / 8; j16 += TK_THREADS) {
        uint4 u = row4[j16];
        uint32_t w[4] = {u.x, u.y, u.z, u.w};
#pragma unroll
        for (int q = 0; q < 4; ++q) {
#pragma unroll
            for (int e = 0; e < 2; ++e) {
                uint32_t k = sortable16((w[q] >> (e * 16)) & 0xFFFFu);
                if (k >= T) {
                    int p = atomicAdd(&nbuf, 1);
                    if (p < TK_BUF) {
                        int j = j16 * 8 + q * 2 + e;
                        buf[p] = (k << 16) | (uint32_t)(8191 - j);
                    }
                }
            }
        }
    }
    __syncthreads();

    if (wid == 0) {
        int count = min(nbuf, TK_BUF);
        for (int r = 0; r < CAND; ++r) {
            uint32_t best = 0; int bp = -1;
            for (int p = lane; p < count; p += 32)
                if (buf[p] > best) { best = buf[p]; bp = p; }
#pragma unroll
            for (int o = 16; o > 0; o >>= 1) {
                uint32_t ob = __shfl_xor_sync(0xffffffffu, best, o);
                int      op = __shfl_xor_sync(0xffffffffu, bp, o);
                if (ob > best) { best = ob; bp = op; }
            }
            if (lane == 0) {
                g_cand[(size_t)i * CAND + r] = 8191 - (int)(best & 0xFFFFu);
                buf[bp] = 0;
            }
            __syncwarp();
        }
    }
}

// ---------------- exact fp32 rescore of 16 candidates -> top-6 ---------------
__device__ __forceinline__ bool better(float v1, int i1, float v2, int i2) {
    return (v1 > v2) || (v1 == v2 && i1 < i2);
}

__global__ void rescore_kernel() {
    int i = blockIdx.x;
    int tid = threadIdx.x;
    int wid = tid >> 5, lane = tid & 31;
    __shared__ float xi[DIM];
    __shared__ int cand[CAND];
    __shared__ float red[CAND][8];
    for (int d = tid; d < DIM; d += 256) xi[d] = g_xn[(size_t)i * DIM + d];
    if (tid < CAND) cand[tid] = g_cand[(size_t)i * CAND + tid];
    __syncthreads();

    float acc[CAND];
#pragma unroll
    for (int c = 0; c < CAND; ++c) acc[c] = 0.f;
    for (int d = tid; d < DIM; d += 256) {
        float xv = xi[d];
#pragma unroll
        for (int c = 0; c < CAND; ++c)
            acc[c] += xv * g_xn[(size_t)cand[c] * DIM + d];
    }
#pragma unroll
    for (int c = 0; c < CAND; ++c) {
#pragma unroll
        for (int o = 16; o > 0; o >>= 1)
            acc[c] += __shfl_xor_sync(0xffffffffu, acc[c], o);
        if (lane == 0) red[c][wid] = acc[c];
    }
    __syncthreads();
    if (tid == 0) {
        float cv[CAND]; int ci[CAND];
#pragma unroll
        for (int c = 0; c < CAND; ++c) {
            float s = 0.f;
#pragma unroll
            for (int w = 0; w < 8; ++w) s += red[c][w];
            cv[c] = s; ci[c] = cand[c];
        }
        for (int r = 0; r < KNN; ++r) {
            int bp = r;
            for (int c = r + 1; c < CAND; ++c)
                if (better(cv[c], ci[c], cv[bp], ci[bp])) bp = c;
            float tv = cv[r]; cv[r] = cv[bp]; cv[bp] = tv;
            int   ti = ci[r]; ci[r] = ci[bp]; ci[bp] = ti;
            g_idx[(size_t)i * KNN + r] = ci[r];
        }
    }
}

// ---------------- k-reciprocal + GIN aggregation -> h0 splits ----------------
__global__ void aggr_kernel(const float* __restrict__ x) {
    int i = blockIdx.x;
    int tid = threadIdx.x;
    __shared__ int nb[KNN];
    __shared__ int ok[KNN];
    if (tid < KNN) {
        int j = g_idx[(size_t)i * KNN + tid];
        nb[tid] = j;
        int r = 0;
#pragma unroll
        for (int t = 0; t < KNN; ++t) r |= (g_idx[(size_t)j * KNN + t] == i);
        ok[tid] = r;
    }
    __syncthreads();
    for (int d = tid; d < DIM; d += 256) {
        float acc = GIN_ONE_PLUS_EPS * x[(size_t)i * DIM + d];
#pragma unroll
        for (int c = 0; c < KNN; ++c)
            if (ok[c]) acc += x[(size_t)nb[c] * DIM + d];
        __nv_bfloat16 h = __float2bfloat16(acc);
        ((__nv_bfloat16*)g_sh)[(size_t)i * DIM + d] = h;
        ((__nv_bfloat16*)g_sl)[(size_t)i * DIM + d] =
            __float2bfloat16(acc - __bfloat162float(h));
    }
}

// ---------------- BatchNorm (training-mode batch stats) ----------------------
__global__ void bn_zero_kernel() {
    int c = blockIdx.x * 256 + threadIdx.x;
    if (c < DIM) { g_scale[c] = 0.f; g_shift[c] = 0.f; }
}

__global__ void bn_stats_kernel() {
    int c  = blockIdx.x * 256 + threadIdx.x;
    int r0 = blockIdx.y * 256;
    float s = 0.f, q = 0.f;
    for (int r = r0; r < r0 + 256; ++r) {
        float v = g_h2[(size_t)r * DIM + c];
        s += v; q += v * v;
    }
    atomicAdd(&g_scale[c], s);
    atomicAdd(&g_shift[c], q);
}

__global__ void bn_finalize_kernel(const float* __restrict__ gamma,
                                   const float* __restrict__ beta) {
    int c = blockIdx.x * 256 + threadIdx.x;
    if (c >= DIM) return;
    const float invN = 1.f / (float)N_PTS;
    float mean = g_scale[c] * invN;
    float var  = g_shift[c] * invN - mean * mean;
    float sc   = gamma[c] * rsqrtf(var + BN_EPS);
    g_scale[c] = sc;
    g_shift[c] = beta[c] - mean * sc;
}

__global__ void bn_apply_kernel() {
    size_t idx = (size_t)blockIdx.x * 256 + threadIdx.x;
    int c = (int)(idx & (DIM - 1));
    float v = g_h2[idx] * g_scale[c] + g_shift[c];
    __nv_bfloat16 h = __float2bfloat16(v);
    ((__nv_bfloat16*)g_sh)[idx] = h;
    ((__nv_bfloat16*)g_sl)[idx] = __float2bfloat16(v - __bfloat162float(h));
}

// ---------------- launch -----------------------------------------------------
extern "C" void kernel_launch(void* const* d_in, const int* in_sizes, int n_in,
                              void* d_out, int out_size) {
    const float* x     = (const float*)d_in[0];
    const float* w1    = (const float*)d_in[1];
    const float* b1    = (const float*)d_in[2];
    const float* w2    = (const float*)d_in[3];
    const float* b2    = (const float*)d_in[4];
    const float* gamma = (const float*)d_in[5];
    const float* beta  = (const float*)d_in[6];
    const float* wc    = (const float*)d_in[7];
    float* out = (float*)d_out;

    cudaFuncSetAttribute(gemm_mma, cudaFuncAttributeMaxDynamicSharedMemorySize, SMEM_GEMM);
    cudaFuncSetAttribute(sim_fp8,  cudaFuncAttributeMaxDynamicSharedMemorySize, SMEM_GEMM);

    float *p_xn, *p_h2;
    unsigned char* p_x8;
    unsigned short *p_sim, *p_sh, *p_sl, *p_th, *p_tl;
    unsigned short *p_w1h, *p_w1l, *p_w2h, *p_w2l, *p_wch, *p_wcl;
    cudaGetSymbolAddress((void**)&p_xn,  g_xn);
    cudaGetSymbolAddress((void**)&p_x8,  g_x8);
    cudaGetSymbolAddress((void**)&p_sim, g_sim);
    cudaGetSymbolAddress((void**)&p_h2,  g_h2);
    cudaGetSymbolAddress((void**)&p_sh,  g_sh);
    cudaGetSymbolAddress((void**)&p_sl,  g_sl);
    cudaGetSymbolAddress((void**)&p_th,  g_th);
    cudaGetSymbolAddress((void**)&p_tl,  g_tl);
    cudaGetSymbolAddress((void**)&p_w1h, g_w1h);
    cudaGetSymbolAddress((void**)&p_w1l, g_w1l);
    cudaGetSymbolAddress((void**)&p_w2h, g_w2h);
    cudaGetSymbolAddress((void**)&p_w2l, g_w2l);
    cudaGetSymbolAddress((void**)&p_wch, g_wch);
    cudaGetSymbolAddress((void**)&p_wcl, g_wcl);

    const size_t nDD = (size_t)DIM * DIM;
    const size_t nCD = (size_t)NCLS * DIM;
    const size_t nND = (size_t)N_PTS * DIM;

    normalize_kernel<<<N_PTS, 256>>>(x);
    split_kernel<<<(unsigned)((nDD + 255) / 256), 256>>>(w1, p_w1h, p_w1l, nDD);
    split_kernel<<<(unsigned)((nDD + 255) / 256), 256>>>(w2, p_w2h, p_w2l, nDD);

    // similarity (fp8 e4m3 HMMA, symmetric, bf16 raw-scale sims)
    sim_fp8<<<dim3(64, 64), 256, SMEM_GEMM>>>(p_x8, p_sim);

    split_kernel<<<(unsigned)((nCD + 255) / 256), 256>>>(wc, p_wch, p_wcl, nCD);

    // radix-select top-16 candidates, exact fp32 rescore -> top-6
    topk_kernel<<<N_PTS, TK_THREADS>>>();
    rescore_kernel<<<N_PTS, 256>>>();

    // k-reciprocal + GIN aggregation -> h0 splits
    aggr_kernel<<<N_PTS, 256>>>(x);

    // MLP layer 1 (bf16x3): relu(h0 @ w1^T + b1) -> h1 splits
    gemm_mma<<<dim3(16, 64), 128, SMEM_GEMM>>>(
        (const __nv_bfloat16*)p_sh, (const __nv_bfloat16*)p_sl,
        (const __nv_bfloat16*)p_w1h, (const __nv_bfloat16*)p_w1l,
        nullptr, p_th, p_tl, N_PTS, DIM, DIM, b1, 1, 1);

    // MLP layer 2 (bf16x3): h1 @ w2^T + b2 -> h2 fp32
    gemm_mma<<<dim3(16, 64), 128, SMEM_GEMM>>>(
        (const __nv_bfloat16*)p_th, (const __nv_bfloat16*)p_tl,
        (const __nv_bfloat16*)p_w2h, (const __nv_bfloat16*)p_w2l,
        p_h2, nullptr, nullptr, N_PTS, DIM, DIM, b2, 0, 0);

    // BatchNorm -> hn splits
    bn_zero_kernel<<<(DIM + 255) / 256, 256>>>();
    bn_stats_kernel<<<dim3(DIM / 256, N_PTS / 256), 256>>>();
    bn_finalize_kernel<<<(DIM + 255) / 256, 256>>>(gamma, beta);
    bn_apply_kernel<<<(unsigned)(nND / 256), 256>>>();

    // classifier (bf16x3): hn @ wc^T -> out [8192, 751]
    gemm_mma<<<dim3((NCLS + 127) / 128, 64), 128, SMEM_GEMM>>>(
        (const __nv_bfloat16*)p_sh, (const __nv_bfloat16*)p_sl,
        (const __nv_bfloat16*)p_wch, (const __nv_bfloat16*)p_wcl,
        out, nullptr, nullptr, N_PTS, NCLS, DIM, nullptr, 0, 0);
}

// round 14
// speedup vs baseline: 1.0255x; 1.0006x over previous
#include <cuda_runtime.h>
#include <cuda_bf16.h>
#include <cuda_fp8.h>
#include <cstdint>
#include <math.h>

#define N_PTS 8192
#define DIM   2048
#define NCLS  751
#define KNN   6
#define CAND  16
#define GIN_ONE_PLUS_EPS 1.3f
#define BN_EPS 1e-5f
#define FP8_SCALE 256.0f

// ---------------- scratch ----------------------------------------------------
__device__ float g_xn [(size_t)N_PTS * DIM];
__device__ unsigned char g_x8 [(size_t)N_PTS * DIM];      // e4m3 of xn*256
__device__ unsigned short g_sim[(size_t)N_PTS * N_PTS];   // bf16 sims (raw scale)
__device__ int   g_cand[(size_t)N_PTS * CAND];
__device__ int   g_idx[(size_t)N_PTS * KNN];
__device__ float g_h2 [(size_t)N_PTS * DIM];
__device__ unsigned short g_sh [(size_t)N_PTS * DIM];     // act split hi (h0, later hn)
__device__ unsigned short g_sl [(size_t)N_PTS * DIM];     // act split lo
__device__ unsigned short g_th [(size_t)N_PTS * DIM];     // h1 split hi
__device__ unsigned short g_tl [(size_t)N_PTS * DIM];     // h1 split lo
__device__ unsigned short g_w1h[(size_t)DIM * DIM], g_w1l[(size_t)DIM * DIM];
__device__ unsigned short g_w2h[(size_t)DIM * DIM], g_w2l[(size_t)DIM * DIM];
__device__ unsigned short g_wch[(size_t)NCLS * DIM], g_wcl[(size_t)NCLS * DIM];
__device__ float g_scale[DIM];
__device__ float g_shift[DIM];

// ---------------- helpers ----------------------------------------------------
__device__ __forceinline__ uint32_t smem_to_u32(const void* p) {
    uint32_t a;
    asm("{ .reg .u64 t; cvta.to.shared.u64 t, %1; cvt.u32.u64 %0, t; }" : "=r"(a) : "l"(p));
    return a;
}

__device__ __forceinline__ void cp_async16(uint32_t dst, const void* src, int valid) {
    asm volatile("cp.async.cg.shared.global [%0], [%1], 16, %2;"
                 :: "r"(dst), "l"(src), "r"(valid ? 16 : 0) : "memory");
}
__device__ __forceinline__ void cp_commit() {
    asm volatile("cp.async.commit_group;" ::: "memory");
}
template <int N>
__device__ __forceinline__ void cp_wait() {
    asm volatile("cp.async.wait_group %0;" :: "n"(N) : "memory");
}

__device__ __forceinline__ void ldm_x4(uint32_t* r, uint32_t addr) {
    asm volatile("ldmatrix.sync.aligned.m8n8.x4.shared.b16 {%0,%1,%2,%3}, [%4];"
                 : "=r"(r[0]), "=r"(r[1]), "=r"(r[2]), "=r"(r[3]) : "r"(addr));
}

__device__ __forceinline__ void mma16816(float* d, const uint32_t* a, uint32_t b0, uint32_t b1) {
    asm volatile("mma.sync.aligned.m16n8k16.row.col.f32.bf16.bf16.f32 "
                 "{%0,%1,%2,%3}, {%4,%5,%6,%7}, {%8,%9}, {%0,%1,%2,%3};"
                 : "+f"(d[0]), "+f"(d[1]), "+f"(d[2]), "+f"(d[3])
                 : "r"(a[0]), "r"(a[1]), "r"(a[2]), "r"(a[3]), "r"(b0), "r"(b1));
}

__device__ __forceinline__ void mma16832_fp8(float* d, const uint32_t* a, uint32_t b0, uint32_t b1) {
    asm volatile("mma.sync.aligned.m16n8k32.row.col.f32.e4m3.e4m3.f32 "
                 "{%0,%1,%2,%3}, {%4,%5,%6,%7}, {%8,%9}, {%0,%1,%2,%3};"
                 : "+f"(d[0]), "+f"(d[1]), "+f"(d[2]), "+f"(d[3])
                 : "r"(a[0]), "r"(a[1]), "r"(a[2]), "r"(a[3]), "r"(b0), "r"(b1));
}

__device__ __forceinline__ uint32_t pack_split_hi(float v0, float v1, uint32_t& lo_pack) {
    __nv_bfloat16 h0 = __float2bfloat16(v0);
    __nv_bfloat16 h1 = __float2bfloat16(v1);
    __nv_bfloat16 l0 = __float2bfloat16(v0 - __bfloat162float(h0));
    __nv_bfloat16 l1 = __float2bfloat16(v1 - __bfloat162float(h1));
    unsigned short uh0 = *(unsigned short*)&h0, uh1 = *(unsigned short*)&h1;
    unsigned short ul0 = *(unsigned short*)&l0, ul1 = *(unsigned short*)&l1;
    lo_pack = (uint32_t)ul0 | ((uint32_t)ul1 << 16);
    return (uint32_t)uh0 | ((uint32_t)uh1 << 16);
}

// bf16 bit pattern -> order-preserving 16-bit key (bigger = larger value)
__device__ __forceinline__ uint32_t sortable16(uint32_t us) {
    return (us & 0x8000u) ? (~us & 0xFFFFu) : (us | 0x8000u);
}

#define SMEM_GEMM 66048   // max(2*32768 pipeline, 128*129*4 transpose stage)

// ---------------- fp8 similarity GEMM: C = X*X^T (bf16 out, raw scale) -------
// 128x128 CTA tile, BK=128 fp8 bytes, 128 thr (4 warps 2x2, warp tile 64x64),
// cp.async double buffer, swizzled smem, 2 CTAs/SM. Symmetric: bx<=by
// computed; mirror tile via smem transpose.
__global__ __launch_bounds__(128, 2)
void sim_fp8(const unsigned char* __restrict__ X, unsigned short* __restrict__ C)
{
    const int bx = blockIdx.x, by = blockIdx.y;
    if (bx > by) return;

    extern __shared__ char smem[];
    const uint32_t sb = smem_to_u32(smem);
    const int tid = threadIdx.x;
    const int lane = tid & 31;
    const int wid = tid >> 5;
    const int wm = wid & 1;
    const int wn = wid >> 1;
    const int wRow = wm * 64, wCol = wn * 64;

    const int rowBase = by * 128;
    const int colBase = bx * 128;
    const int nchunk = DIM / 128;          // 16

    float acc[4][8][4];
#pragma unroll
    for (int i = 0; i < 4; ++i)
#pragma unroll
        for (int j = 0; j < 8; ++j)
#pragma unroll
            for (int q = 0; q < 4; ++q) acc[i][j][q] = 0.f;

    auto load_chunk = [&](int c) {
        const int k0 = c * 128;
        const uint32_t base = sb + (uint32_t)(c & 1) * 32768u;
#pragma unroll
        for (int i = 0; i < 8; ++i) {      // A tile: 128 rows x 128B
            const int u = tid + i * 128;
            const int r = u >> 3, ku = u & 7;
            cp_async16(base + (uint32_t)(r * 8 + (ku ^ (r & 7))) * 16,
                       X + (size_t)(rowBase + r) * DIM + k0 + ku * 16, 1);
        }
#pragma unroll
        for (int i = 0; i < 8; ++i) {      // B tile
            const int u = tid + i * 128;
            const int r = u >> 3, ku = u & 7;
            cp_async16(base + 16384u + (uint32_t)(r * 8 + (ku ^ (r & 7))) * 16,
                       X + (size_t)(colBase + r) * DIM + k0 + ku * 16, 1);
        }
        cp_commit();
    };

    load_chunk(0);

    for (int c = 0; c < nchunk; ++c) {
        if (c + 1 < nchunk) { load_chunk(c + 1); cp_wait<1>(); }
        else                { cp_wait<0>(); }
        __syncthreads();

        const uint32_t base = sb + (uint32_t)(c & 1) * 32768u;
#pragma unroll
        for (int s = 0; s < 4; ++s) {      // four k32 steps (32B each)
            uint32_t a[4][4];
#pragma unroll
            for (int i = 0; i < 4; ++i) {
                const int r = wRow + i * 16 + (lane & 15);
                const int ku = s * 2 + (lane >> 4);
                ldm_x4(a[i], base + (uint32_t)(r * 8 + (ku ^ (r & 7))) * 16);
            }
            uint32_t bf[4][4];
#pragma unroll
            for (int j = 0; j < 4; ++j) {
                const int rn = wCol + j * 16 + (lane & 7) + ((lane >> 4) << 3);
                const int ku = s * 2 + ((lane >> 3) & 1);
                ldm_x4(bf[j], base + 16384u + (uint32_t)(rn * 8 + (ku ^ (rn & 7))) * 16);
            }
#pragma unroll
            for (int i = 0; i < 4; ++i)
#pragma unroll
                for (int j = 0; j < 4; ++j) {
                    mma16832_fp8(acc[i][j * 2 + 0], a[i], bf[j][0], bf[j][1]);
                    mma16832_fp8(acc[i][j * 2 + 1], a[i], bf[j][2], bf[j][3]);
                }
        }
        __syncthreads();
    }

    // ---- epilogue: bf16 pair stores ----
#pragma unroll
    for (int i = 0; i < 4; ++i) {
        const int row = rowBase + wRow + i * 16 + (lane >> 2);
#pragma unroll
        for (int j = 0; j < 8; ++j) {
            const int col = colBase + wCol + j * 8 + (lane & 3) * 2;
#pragma unroll
            for (int h = 0; h < 2; ++h) {
                const int rr = row + h * 8;
                __nv_bfloat16 b0 = __float2bfloat16(acc[i][j][h * 2 + 0]);
                __nv_bfloat16 b1 = __float2bfloat16(acc[i][j][h * 2 + 1]);
                uint32_t pk = (uint32_t)(*(unsigned short*)&b0) |
                              ((uint32_t)(*(unsigned short*)&b1) << 16);
                *(uint32_t*)(C + (size_t)rr * N_PTS + col) = pk;
            }
        }
    }

    // ---- mirror tile ----
    if (bx < by) {
        __syncthreads();
        float* sc = (float*)smem;          // [128][129]
#pragma unroll
        for (int i = 0; i < 4; ++i) {
            const int lr = wRow + i * 16 + (lane >> 2);
#pragma unroll
            for (int j = 0; j < 8; ++j) {
                const int lc = wCol + j * 8 + (lane & 3) * 2;
                sc[(lr    ) * 129 + lc    ] = acc[i][j][0];
                sc[(lr    ) * 129 + lc + 1] = acc[i][j][1];
                sc[(lr + 8) * 129 + lc    ] = acc[i][j][2];
                sc[(lr + 8) * 129 + lc + 1] = acc[i][j][3];
            }
        }
        __syncthreads();
        for (int cc = 0; cc < 128; ++cc) {
            __nv_bfloat16 b = __float2bfloat16(sc[tid * 129 + cc]);
            C[(size_t)(colBase + cc) * N_PTS + rowBase + tid] = *(unsigned short*)&b;
        }
    }
}

// ---------------- bf16 mma.sync GEMM: C[M,Nc] = A[M,K] * B[Nc,K]^T ----------
__global__ __launch_bounds__(128, 2)
void gemm_mma(const __nv_bfloat16* __restrict__ Ah, const __nv_bfloat16* __restrict__ Al,
              const __nv_bfloat16* __restrict__ Bh, const __nv_bfloat16* __restrict__ Bl,
              float* __restrict__ Cf,
              unsigned short* __restrict__ Chi, unsigned short* __restrict__ Clo,
              int M, int Nc, int Kd,
              const float* __restrict__ bias, int relu, int omode)
{
    const int bx = blockIdx.x, by = blockIdx.y;
    extern __shared__ char smem[];
    const uint32_t sb = smem_to_u32(smem);
    const int tid = threadIdx.x;
    const int lane = tid & 31;
    const int wid = tid >> 5;
    const int wm = wid & 1;
    const int wn = wid >> 1;
    const int wRow = wm * 64, wCol = wn * 64;

    const int rowBase = by * 128;
    const int colBase = bx * 128;
    const int kcount = Kd / 64;
    const int nchunk = 3 * kcount;

    float acc[4][8][4];
#pragma unroll
    for (int i = 0; i < 4; ++i)
#pragma unroll
        for (int j = 0; j < 8; ++j)
#pragma unroll
            for (int q = 0; q < 4; ++q) acc[i][j][q] = 0.f;

    auto load_chunk = [&](int c) {
        const int pass = c / kcount;
        const int k0 = (c % kcount) * 64;
        const __nv_bfloat16* As = (pass == 2) ? Al : Ah;
        const __nv_bfloat16* Bs = (pass == 1) ? Bl : Bh;
        const uint32_t base = sb + (uint32_t)(c & 1) * 32768u;
#pragma unroll
        for (int i = 0; i < 8; ++i) {
            const int u = tid + i * 128;
            const int r = u >> 3, ku = u & 7;
            const int grow = rowBase + r;
            cp_async16(base + (uint32_t)(r * 8 + (ku ^ (r & 7))) * 16,
                       As + (size_t)grow * Kd + k0 + ku * 8, grow < M);
        }
#pragma unroll
        for (int i = 0; i < 8; ++i) {
            const int u = tid + i * 128;
            const int r = u >> 3, ku = u & 7;
            const int grow = colBase + r;
            cp_async16(base + 16384u + (uint32_t)(r * 8 + (ku ^ (r & 7))) * 16,
                       Bs + (size_t)grow * Kd + k0 + ku * 8, grow < Nc);
        }
        cp_commit();
    };

    load_chunk(0);

    for (int c = 0; c < nchunk; ++c) {
        if (c + 1 < nchunk) { load_chunk(c + 1); cp_wait<1>(); }
        else                { cp_wait<0>(); }
        __syncthreads();

        const uint32_t base = sb + (uint32_t)(c & 1) * 32768u;
#pragma unroll
        for (int s = 0; s < 4; ++s) {
            uint32_t a[4][4];
#pragma unroll
            for (int i = 0; i < 4; ++i) {
                const int r = wRow + i * 16 + (lane & 15);
                const int ku = s * 2 + (lane >> 4);
                ldm_x4(a[i], base + (uint32_t)(r * 8 + (ku ^ (r & 7))) * 16);
            }
            uint32_t bf[4][4];
#pragma unroll
            for (int j = 0; j < 4; ++j) {
                const int rn = wCol + j * 16 + (lane & 7) + ((lane >> 4) << 3);
                const int ku = s * 2 + ((lane >> 3) & 1);
                ldm_x4(bf[j], base + 16384u + (uint32_t)(rn * 8 + (ku ^ (rn & 7))) * 16);
            }
#pragma unroll
            for (int i = 0; i < 4; ++i)
#pragma unroll
                for (int j = 0; j < 4; ++j) {
                    mma16816(acc[i][j * 2 + 0], a[i], bf[j][0], bf[j][1]);
                    mma16816(acc[i][j * 2 + 1], a[i], bf[j][2], bf[j][3]);
                }
        }
        __syncthreads();
    }

#pragma unroll
    for (int i = 0; i < 4; ++i) {
        const int row = rowBase + wRow + i * 16 + (lane >> 2);
#pragma unroll
        for (int j = 0; j < 8; ++j) {
            const int col = colBase + wCol + j * 8 + (lane & 3) * 2;
#pragma unroll
            for (int h = 0; h < 2; ++h) {
                const int rr = row + h * 8;
                if (rr < M) {
                    float v0 = acc[i][j][h * 2 + 0];
                    float v1 = acc[i][j][h * 2 + 1];
                    if (bias) {
                        if (col     < Nc) v0 += __ldg(bias + col);
                        if (col + 1 < Nc) v1 += __ldg(bias + col + 1);
                    }
                    if (relu) { v0 = fmaxf(v0, 0.f); v1 = fmaxf(v1, 0.f); }
                    if (omode == 0) {
                        if (col     < Nc) Cf[(size_t)rr * Nc + col]     = v0;
                        if (col + 1 < Nc) Cf[(size_t)rr * Nc + col + 1] = v1;
                    } else if (col + 1 < Nc) {
                        uint32_t lo_pack;
                        uint32_t hi_pack = pack_split_hi(v0, v1, lo_pack);
                        *(uint32_t*)(Chi + (size_t)rr * Nc + col) = hi_pack;
                        *(uint32_t*)(Clo + (size_t)rr * Nc + col) = lo_pack;
                    }
                }
            }
        }
    }
}

// ---------------- row L2 normalize (fp32 + fp8 copy) -------------------------
__global__ void normalize_kernel(const float* __restrict__ x) {
    int i = blockIdx.x;
    int tid = threadIdx.x;
    const float* xi = x + (size_t)i * DIM;
    float s = 0.f;
    for (int d = tid; d < DIM; d += 256) { float v = xi[d]; s += v * v; }
    __shared__ float sh[256];
    sh[tid] = s; __syncthreads();
    for (int o = 128; o > 0; o >>= 1) {
        if (tid < o) sh[tid] += sh[tid + o];
        __syncthreads();
    }
    float inv = 1.f / fmaxf(sqrtf(sh[0]), 1e-12f);
    float* out = g_xn + (size_t)i * DIM;
    unsigned char* out8 = g_x8 + (size_t)i * DIM;
    for (int d = tid; d < DIM; d += 256) {
        float v = xi[d] * inv;
        out[d] = v;
        out8[d] = (unsigned char)__nv_cvt_float_to_fp8(v * FP8_SCALE,
                                                       __NV_SATFINITE, __NV_E4M3);
    }
}

// ---------------- bf16 hi/lo split (weights only) ----------------------------
__global__ void split_kernel(const float* __restrict__ src,
                             unsigned short* __restrict__ hi,
                             unsigned short* __restrict__ lo, size_t n) {
    size_t i = (size_t)blockIdx.x * 256 + threadIdx.x;
    if (i >= n) return;
    float v = src[i];
    __nv_bfloat16 h = __float2bfloat16(v);
    ((__nv_bfloat16*)hi)[i] = h;
    ((__nv_bfloat16*)lo)[i] = __float2bfloat16(v - __bfloat162float(h));
}

// ---------------- radix-select exact per-row top-16 (bf16 sims) --------------
// pass 1 uses warp-aggregated histogramming (__match_any_sync): one atomic
// per distinct bin per warp-step instead of per element.
#define TK_THREADS 256
#define TK_BUF 1024

__global__ __launch_bounds__(TK_THREADS)
void topk_kernel() {
    const int i = blockIdx.x;
    const int tid = threadIdx.x;
    const int wid = tid >> 5, lane = tid & 31;
    const uint4* row4 = (const uint4*)(g_sim + (size_t)i * N_PTS);

    __shared__ int hist[256];
    __shared__ int hist2[256];
    __shared__ uint32_t buf[TK_BUF];
    __shared__ int nbuf;
    __shared__ int s_b, s_cntAbove;
    __shared__ uint32_t s_T;

    for (int b = tid; b < 256; b += TK_THREADS) { hist[b] = 0; hist2[b] = 0; }
    if (tid == 0) nbuf = 0;
    __syncthreads();

    // pass 1: high-byte histogram, warp-aggregated
    for (int j16 = tid; j16 < N_PTS / 8; j16 += TK_THREADS) {
        uint4 u = row4[j16];
        uint32_t w[4] = {u.x, u.y, u.z, u.w};
#pragma unroll
        for (int q = 0; q < 4; ++q) {
#pragma unroll
            for (int e = 0; e < 2; ++e) {
                uint32_t bin = sortable16((w[q] >> (e * 16)) & 0xFFFFu) >> 8;
                unsigned m = __match_any_sync(0xffffffffu, bin);
                if (lane == (__ffs(m) - 1))
                    atomicAdd(&hist[bin], __popc(m));
            }
        }
    }
    __syncthreads();
    if (tid == 0) {
        int cum = 0, b = 255;
        for (; b > 0; --b) {
            if (cum + hist[b] >= CAND) break;
            cum += hist[b];
        }
        s_b = b; s_cntAbove = cum;
    }
    __syncthreads();
    const uint32_t bstar = (uint32_t)s_b;

    // pass 2: low-byte histogram within bstar (few hits -> direct atomics)
    for (int j16 = tid; j16 < N_PTS / 8; j16 += TK_THREADS) {
        uint4 u = row4[j16];
        uint32_t w[4] = {u.x, u.y, u.z, u.w};
#pragma unroll
        for (int q = 0; q < 4; ++q) {
#pragma unroll
            for (int e = 0; e < 2; ++e) {
                uint32_t k = sortable16((w[q] >> (e * 16)) & 0xFFFFu);
                if ((k >> 8) == bstar) atomicAdd(&hist2[k & 0xFFu], 1);
            }
        }
    }
    __syncthreads();
    if (tid == 0) {
        int cum = s_cntAbove, s = 255;
        for (; s > 0; --s) {
            if (cum + hist2[s] >= CAND) break;
            cum += hist2[s];
        }
        s_T = (bstar << 8) | (uint32_t)s;
    }
    __syncthreads();
    const uint32_t T = s_T;

    // pass 3: compact all keys >= T
    for (int j16 = tid; j16 < N_PTS / 8; j16 += TK_THREADS) {
        uint4 u = row4[j16];
        uint32_t w[4] = {u.x, u.y, u.z, u.w};
#pragma unroll
        for (int q = 0; q < 4; ++q) {
#pragma unroll
            for (int e = 0; e < 2; ++e) {
                uint32_t k = sortable16((w[q] >> (e * 16)) & 0xFFFFu);
                if (k >= T) {
                    int p = atomicAdd(&nbuf, 1);
                    if (p < TK_BUF) {
                        int j = j16 * 8 + q * 2 + e;
                        buf[p] = (k << 16) | (uint32_t)(8191 - j);
                    }
                }
            }
        }
    }
    __syncthreads();

    // warp 0: extract top-CAND (value desc, then lower index)
    if (wid == 0) {
        int count = min(nbuf, TK_BUF);
        for (int r = 0; r < CAND; ++r) {
            uint32_t best = 0; int bp = -1;
            for (int p = lane; p < count; p += 32)
                if (buf[p] > best) { best = buf[p]; bp = p; }
#pragma unroll
            for (int o = 16; o > 0; o >>= 1) {
                uint32_t ob = __shfl_xor_sync(0xffffffffu, best, o);
                int      op = __shfl_xor_sync(0xffffffffu, bp, o);
                if (ob > best) { best = ob; bp = op; }
            }
            if (lane == 0) {
                g_cand[(size_t)i * CAND + r] = 8191 - (int)(best & 0xFFFFu);
                buf[bp] = 0;
            }
            __syncwarp();
        }
    }
}

// ---------------- exact fp32 rescore of 16 candidates -> top-6 ---------------
__device__ __forceinline__ bool better(float v1, int i1, float v2, int i2) {
    return (v1 > v2) || (v1 == v2 && i1 < i2);
}

__global__ void rescore_kernel() {
    int i = blockIdx.x;
    int tid = threadIdx.x;
    int wid = tid >> 5, lane = tid & 31;
    __shared__ float xi[DIM];
    __shared__ int cand[CAND];
    __shared__ float red[CAND][8];
    for (int d = tid; d < DIM; d += 256) xi[d] = g_xn[(size_t)i * DIM + d];
    if (tid < CAND) cand[tid] = g_cand[(size_t)i * CAND + tid];
    __syncthreads();

    float acc[CAND];
#pragma unroll
    for (int c = 0; c < CAND; ++c) acc[c] = 0.f;
    for (int d = tid; d < DIM; d += 256) {
        float xv = xi[d];
#pragma unroll
        for (int c = 0; c < CAND; ++c)
            acc[c] += xv * g_xn[(size_t)cand[c] * DIM + d];
    }
#pragma unroll
    for (int c = 0; c < CAND; ++c) {
#pragma unroll
        for (int o = 16; o > 0; o >>= 1)
            acc[c] += __shfl_xor_sync(0xffffffffu, acc[c], o);
        if (lane == 0) red[c][wid] = acc[c];
    }
    __syncthreads();
    if (tid == 0) {
        float cv[CAND]; int ci[CAND];
#pragma unroll
        for (int c = 0; c < CAND; ++c) {
            float s = 0.f;
#pragma unroll
            for (int w = 0; w < 8; ++w) s += red[c][w];
            cv[c] = s; ci[c] = cand[c];
        }
        for (int r = 0; r < KNN; ++r) {
            int bp = r;
            for (int c = r + 1; c < CAND; ++c)
                if (better(cv[c], ci[c], cv[bp], ci[bp])) bp = c;
            float tv = cv[r]; cv[r] = cv[bp]; cv[bp] = tv;
            int   ti = ci[r]; ci[r] = ci[bp]; ci[bp] = ti;
            g_idx[(size_t)i * KNN + r] = ci[r];
        }
    }
}

// ---------------- k-reciprocal + GIN aggregation -> h0 splits ----------------
__global__ void aggr_kernel(const float* __restrict__ x) {
    int i = blockIdx.x;
    int tid = threadIdx.x;
    __shared__ int nb[KNN];
    __shared__ int ok[KNN];
    if (tid < KNN) {
        int j = g_idx[(size_t)i * KNN + tid];
        nb[tid] = j;
        int r = 0;
#pragma unroll
        for (int t = 0; t < KNN; ++t) r |= (g_idx[(size_t)j * KNN + t] == i);
        ok[tid] = r;
    }
    __syncthreads();
    for (int d = tid; d < DIM; d += 256) {
        float acc = GIN_ONE_PLUS_EPS * x[(size_t)i * DIM + d];
#pragma unroll
        for (int c = 0; c < KNN; ++c)
            if (ok[c]) acc += x[(size_t)nb[c] * DIM + d];
        __nv_bfloat16 h = __float2bfloat16(acc);
        ((__nv_bfloat16*)g_sh)[(size_t)i * DIM + d] = h;
        ((__nv_bfloat16*)g_sl)[(size_t)i * DIM + d] =
            __float2bfloat16(acc - __bfloat162float(h));
    }
}

// ---------------- BatchNorm (training-mode batch stats) ----------------------
__global__ void bn_zero_kernel() {
    int c = blockIdx.x * 256 + threadIdx.x;
    if (c < DIM) { g_scale[c] = 0.f; g_shift[c] = 0.f; }
}

__global__ void bn_stats_kernel() {
    int c  = blockIdx.x * 256 + threadIdx.x;
    int r0 = blockIdx.y * 256;
    float s = 0.f, q = 0.f;
    for (int r = r0; r < r0 + 256; ++r) {
        float v = g_h2[(size_t)r * DIM + c];
        s += v; q += v * v;
    }
    atomicAdd(&g_scale[c], s);
    atomicAdd(&g_shift[c], q);
}

__global__ void bn_finalize_kernel(const float* __restrict__ gamma,
                                   const float* __restrict__ beta) {
    int c = blockIdx.x * 256 + threadIdx.x;
    if (c >= DIM) return;
    const float invN = 1.f / (float)N_PTS;
    float mean = g_scale[c] * invN;
    float var  = g_shift[c] * invN - mean * mean;
    float sc   = gamma[c] * rsqrtf(var + BN_EPS);
    g_scale[c] = sc;
    g_shift[c] = beta[c] - mean * sc;
}

__global__ void bn_apply_kernel() {
    size_t idx = (size_t)blockIdx.x * 256 + threadIdx.x;
    int c = (int)(idx & (DIM - 1));
    float v = g_h2[idx] * g_scale[c] + g_shift[c];
    __nv_bfloat16 h = __float2bfloat16(v);
    ((__nv_bfloat16*)g_sh)[idx] = h;
    ((__nv_bfloat16*)g_sl)[idx] = __float2bfloat16(v - __bfloat162float(h));
}

// ---------------- launch -----------------------------------------------------
extern "C" void kernel_launch(void* const* d_in, const int* in_sizes, int n_in,
                              void* d_out, int out_size) {
    const float* x     = (const float*)d_in[0];
    const float* w1    = (const float*)d_in[1];
    const float* b1    = (const float*)d_in[2];
    const float* w2    = (const float*)d_in[3];
    const float* b2    = (const float*)d_in[4];
    const float* gamma = (const float*)d_in[5];
    const float* beta  = (const float*)d_in[6];
    const float* wc    = (const float*)d_in[7];
    float* out = (float*)d_out;

    cudaFuncSetAttribute(gemm_mma, cudaFuncAttributeMaxDynamicSharedMemorySize, SMEM_GEMM);
    cudaFuncSetAttribute(sim_fp8,  cudaFuncAttributeMaxDynamicSharedMemorySize, SMEM_GEMM);

    float *p_xn, *p_h2;
    unsigned char* p_x8;
    unsigned short *p_sim, *p_sh, *p_sl, *p_th, *p_tl;
    unsigned short *p_w1h, *p_w1l, *p_w2h, *p_w2l, *p_wch, *p_wcl;
    cudaGetSymbolAddress((void**)&p_xn,  g_xn);
    cudaGetSymbolAddress((void**)&p_x8,  g_x8);
    cudaGetSymbolAddress((void**)&p_sim, g_sim);
    cudaGetSymbolAddress((void**)&p_h2,  g_h2);
    cudaGetSymbolAddress((void**)&p_sh,  g_sh);
    cudaGetSymbolAddress((void**)&p_sl,  g_sl);
    cudaGetSymbolAddress((void**)&p_th,  g_th);
    cudaGetSymbolAddress((void**)&p_tl,  g_tl);
    cudaGetSymbolAddress((void**)&p_w1h, g_w1h);
    cudaGetSymbolAddress((void**)&p_w1l, g_w1l);
    cudaGetSymbolAddress((void**)&p_w2h, g_w2h);
    cudaGetSymbolAddress((void**)&p_w2l, g_w2l);
    cudaGetSymbolAddress((void**)&p_wch, g_wch);
    cudaGetSymbolAddress((void**)&p_wcl, g_wcl);

    const size_t nDD = (size_t)DIM * DIM;
    const size_t nCD = (size_t)NCLS * DIM;
    const size_t nND = (size_t)N_PTS * DIM;

    normalize_kernel<<<N_PTS, 256>>>(x);
    split_kernel<<<(unsigned)((nDD + 255) / 256), 256>>>(w1, p_w1h, p_w1l, nDD);
    split_kernel<<<(unsigned)((nDD + 255) / 256), 256>>>(w2, p_w2h, p_w2l, nDD);

    // similarity (fp8 e4m3 HMMA, symmetric, bf16 raw-scale sims)
    sim_fp8<<<dim3(64, 64), 128, SMEM_GEMM>>>(p_x8, p_sim);

    split_kernel<<<(unsigned)((nCD + 255) / 256), 256>>>(wc, p_wch, p_wcl, nCD);

    // radix-select top-16 candidates, exact fp32 rescore -> top-6
    topk_kernel<<<N_PTS, TK_THREADS>>>();
    rescore_kernel<<<N_PTS, 256>>>();

    // k-reciprocal + GIN aggregation -> h0 splits
    aggr_kernel<<<N_PTS, 256>>>(x);

    // MLP layer 1 (bf16x3): relu(h0 @ w1^T + b1) -> h1 splits
    gemm_mma<<<dim3(16, 64), 128, SMEM_GEMM>>>(
        (const __nv_bfloat16*)p_sh, (const __nv_bfloat16*)p_sl,
        (const __nv_bfloat16*)p_w1h, (const __nv_bfloat16*)p_w1l,
        nullptr, p_th, p_tl, N_PTS, DIM, DIM, b1, 1, 1);

    // MLP layer 2 (bf16x3): h1 @ w2^T + b2 -> h2 fp32
    gemm_mma<<<dim3(16, 64), 128, SMEM_GEMM>>>(
        (const __nv_bfloat16*)p_th, (const __nv_bfloat16*)p_tl,
        (const __nv_bfloat16*)p_w2h, (const __nv_bfloat16*)p_w2l,
        p_h2, nullptr, nullptr, N_PTS, DIM, DIM, b2, 0, 0);

    // BatchNorm -> hn splits
    bn_zero_kernel<<<(DIM + 255) / 256, 256>>>();
    bn_stats_kernel<<<dim3(DIM / 256, N_PTS / 256), 256>>>();
    bn_finalize_kernel<<<(DIM + 255) / 256, 256>>>(gamma, beta);
    bn_apply_kernel<<<(unsigned)(nND / 256), 256>>>();

    // classifier (bf16x3): hn @ wc^T -> out [8192, 751]
    gemm_mma<<<dim3((NCLS + 127) / 128, 64), 128, SMEM_GEMM>>>(
        (const __nv_bfloat16*)p_sh, (const __nv_bfloat16*)p_sl,
        (const __nv_bfloat16*)p_wch, (const __nv_bfloat16*)p_wcl,
        out, nullptr, nullptr, N_PTS, NCLS, DIM, nullptr, 0, 0);
}

// round 15
// speedup vs baseline: 1.5431x; 1.5047x over previous
#include <cuda_runtime.h>
#include <cuda_bf16.h>
#include <cuda_fp16.h>
#include <cuda_fp8.h>
#include <cstdint>
#include <math.h>

#define N_PTS 8192
#define DIM   2048
#define NCLS  751
#define KNN   6
#define CAND  16
#define GIN_ONE_PLUS_EPS 1.3f
#define BN_EPS 1e-5f
#define FP8_SCALE 256.0f

// ---------------- scratch ----------------------------------------------------
__device__ float g_xn [(size_t)N_PTS * DIM];
__device__ unsigned char g_x8 [(size_t)N_PTS * DIM];      // e4m3 of xn*256
__device__ unsigned short g_sim[(size_t)N_PTS * N_PTS];   // bf16 sims (raw scale)
__device__ int   g_cand[(size_t)N_PTS * CAND];
__device__ int   g_idx[(size_t)N_PTS * KNN];
__device__ float g_h2 [(size_t)N_PTS * DIM];
__device__ unsigned short g_sh [(size_t)N_PTS * DIM];     // h0 fp16; later hn bf16-hi
__device__ unsigned short g_sl [(size_t)N_PTS * DIM];     // hn bf16-lo
__device__ unsigned short g_th [(size_t)N_PTS * DIM];     // h1 fp16
__device__ unsigned short g_w1f[(size_t)DIM * DIM];       // w1 fp16
__device__ unsigned short g_w2f[(size_t)DIM * DIM];       // w2 fp16
__device__ unsigned short g_wch[(size_t)NCLS * DIM], g_wcl[(size_t)NCLS * DIM];
__device__ float g_scale[DIM];
__device__ float g_shift[DIM];

// ---------------- helpers ----------------------------------------------------
__device__ __forceinline__ uint32_t smem_to_u32(const void* p) {
    uint32_t a;
    asm("{ .reg .u64 t; cvta.to.shared.u64 t, %1; cvt.u32.u64 %0, t; }" : "=r"(a) : "l"(p));
    return a;
}

__device__ __forceinline__ void cp_async16(uint32_t dst, const void* src, int valid) {
    asm volatile("cp.async.cg.shared.global [%0], [%1], 16, %2;"
                 :: "r"(dst), "l"(src), "r"(valid ? 16 : 0) : "memory");
}
__device__ __forceinline__ void cp_commit() {
    asm volatile("cp.async.commit_group;" ::: "memory");
}
template <int N>
__device__ __forceinline__ void cp_wait() {
    asm volatile("cp.async.wait_group %0;" :: "n"(N) : "memory");
}

__device__ __forceinline__ void ldm_x4(uint32_t* r, uint32_t addr) {
    asm volatile("ldmatrix.sync.aligned.m8n8.x4.shared.b16 {%0,%1,%2,%3}, [%4];"
                 : "=r"(r[0]), "=r"(r[1]), "=r"(r[2]), "=r"(r[3]) : "r"(addr));
}

__device__ __forceinline__ void mma16816_bf(float* d, const uint32_t* a, uint32_t b0, uint32_t b1) {
    asm volatile("mma.sync.aligned.m16n8k16.row.col.f32.bf16.bf16.f32 "
                 "{%0,%1,%2,%3}, {%4,%5,%6,%7}, {%8,%9}, {%0,%1,%2,%3};"
                 : "+f"(d[0]), "+f"(d[1]), "+f"(d[2]), "+f"(d[3])
                 : "r"(a[0]), "r"(a[1]), "r"(a[2]), "r"(a[3]), "r"(b0), "r"(b1));
}

__device__ __forceinline__ void mma16816_f16(float* d, const uint32_t* a, uint32_t b0, uint32_t b1) {
    asm volatile("mma.sync.aligned.m16n8k16.row.col.f32.f16.f16.f32 "
                 "{%0,%1,%2,%3}, {%4,%5,%6,%7}, {%8,%9}, {%0,%1,%2,%3};"
                 : "+f"(d[0]), "+f"(d[1]), "+f"(d[2]), "+f"(d[3])
                 : "r"(a[0]), "r"(a[1]), "r"(a[2]), "r"(a[3]), "r"(b0), "r"(b1));
}

__device__ __forceinline__ void mma16832_fp8(float* d, const uint32_t* a, uint32_t b0, uint32_t b1) {
    asm volatile("mma.sync.aligned.m16n8k32.row.col.f32.e4m3.e4m3.f32 "
                 "{%0,%1,%2,%3}, {%4,%5,%6,%7}, {%8,%9}, {%0,%1,%2,%3};"
                 : "+f"(d[0]), "+f"(d[1]), "+f"(d[2]), "+f"(d[3])
                 : "r"(a[0]), "r"(a[1]), "r"(a[2]), "r"(a[3]), "r"(b0), "r"(b1));
}

__device__ __forceinline__ uint32_t pack_split_hi(float v0, float v1, uint32_t& lo_pack) {
    __nv_bfloat16 h0 = __float2bfloat16(v0);
    __nv_bfloat16 h1 = __float2bfloat16(v1);
    __nv_bfloat16 l0 = __float2bfloat16(v0 - __bfloat162float(h0));
    __nv_bfloat16 l1 = __float2bfloat16(v1 - __bfloat162float(h1));
    unsigned short uh0 = *(unsigned short*)&h0, uh1 = *(unsigned short*)&h1;
    unsigned short ul0 = *(unsigned short*)&l0, ul1 = *(unsigned short*)&l1;
    lo_pack = (uint32_t)ul0 | ((uint32_t)ul1 << 16);
    return (uint32_t)uh0 | ((uint32_t)uh1 << 16);
}

// bf16 bit pattern -> order-preserving 16-bit key (bigger = larger value)
__device__ __forceinline__ uint32_t sortable16(uint32_t us) {
    return (us & 0x8000u) ? (~us & 0xFFFFu) : (us | 0x8000u);
}

#define SMEM_GEMM 66048   // max(2*32768 pipeline, 128*129*4 transpose stage)

// ---------------- fp8 similarity GEMM: C = X*X^T (bf16 out, raw scale) -------
// 128x128 CTA tile, BK=128 fp8 bytes, 128 thr (4 warps 2x2, warp tile 64x64),
// cp.async double buffer, swizzled smem, 2 CTAs/SM. Symmetric.
__global__ __launch_bounds__(128, 2)
void sim_fp8(const unsigned char* __restrict__ X, unsigned short* __restrict__ C)
{
    const int bx = blockIdx.x, by = blockIdx.y;
    if (bx > by) return;

    extern __shared__ char smem[];
    const uint32_t sb = smem_to_u32(smem);
    const int tid = threadIdx.x;
    const int lane = tid & 31;
    const int wid = tid >> 5;
    const int wm = wid & 1;
    const int wn = wid >> 1;
    const int wRow = wm * 64, wCol = wn * 64;

    const int rowBase = by * 128;
    const int colBase = bx * 128;
    const int nchunk = DIM / 128;

    float acc[4][8][4];
#pragma unroll
    for (int i = 0; i < 4; ++i)
#pragma unroll
        for (int j = 0; j < 8; ++j)
#pragma unroll
            for (int q = 0; q < 4; ++q) acc[i][j][q] = 0.f;

    auto load_chunk = [&](int c) {
        const int k0 = c * 128;
        const uint32_t base = sb + (uint32_t)(c & 1) * 32768u;
#pragma unroll
        for (int i = 0; i < 8; ++i) {
            const int u = tid + i * 128;
            const int r = u >> 3, ku = u & 7;
            cp_async16(base + (uint32_t)(r * 8 + (ku ^ (r & 7))) * 16,
                       X + (size_t)(rowBase + r) * DIM + k0 + ku * 16, 1);
        }
#pragma unroll
        for (int i = 0; i < 8; ++i) {
            const int u = tid + i * 128;
            const int r = u >> 3, ku = u & 7;
            cp_async16(base + 16384u + (uint32_t)(r * 8 + (ku ^ (r & 7))) * 16,
                       X + (size_t)(colBase + r) * DIM + k0 + ku * 16, 1);
        }
        cp_commit();
    };

    load_chunk(0);

    for (int c = 0; c < nchunk; ++c) {
        if (c + 1 < nchunk) { load_chunk(c + 1); cp_wait<1>(); }
        else                { cp_wait<0>(); }
        __syncthreads();

        const uint32_t base = sb + (uint32_t)(c & 1) * 32768u;
#pragma unroll
        for (int s = 0; s < 4; ++s) {
            uint32_t a[4][4];
#pragma unroll
            for (int i = 0; i < 4; ++i) {
                const int r = wRow + i * 16 + (lane & 15);
                const int ku = s * 2 + (lane >> 4);
                ldm_x4(a[i], base + (uint32_t)(r * 8 + (ku ^ (r & 7))) * 16);
            }
            uint32_t bf[4][4];
#pragma unroll
            for (int j = 0; j < 4; ++j) {
                const int rn = wCol + j * 16 + (lane & 7) + ((lane >> 4) << 3);
                const int ku = s * 2 + ((lane >> 3) & 1);
                ldm_x4(bf[j], base + 16384u + (uint32_t)(rn * 8 + (ku ^ (rn & 7))) * 16);
            }
#pragma unroll
            for (int i = 0; i < 4; ++i)
#pragma unroll
                for (int j = 0; j < 4; ++j) {
                    mma16832_fp8(acc[i][j * 2 + 0], a[i], bf[j][0], bf[j][1]);
                    mma16832_fp8(acc[i][j * 2 + 1], a[i], bf[j][2], bf[j][3]);
                }
        }
        __syncthreads();
    }

#pragma unroll
    for (int i = 0; i < 4; ++i) {
        const int row = rowBase + wRow + i * 16 + (lane >> 2);
#pragma unroll
        for (int j = 0; j < 8; ++j) {
            const int col = colBase + wCol + j * 8 + (lane & 3) * 2;
#pragma unroll
            for (int h = 0; h < 2; ++h) {
                const int rr = row + h * 8;
                __nv_bfloat16 b0 = __float2bfloat16(acc[i][j][h * 2 + 0]);
                __nv_bfloat16 b1 = __float2bfloat16(acc[i][j][h * 2 + 1]);
                uint32_t pk = (uint32_t)(*(unsigned short*)&b0) |
                              ((uint32_t)(*(unsigned short*)&b1) << 16);
                *(uint32_t*)(C + (size_t)rr * N_PTS + col) = pk;
            }
        }
    }

    if (bx < by) {
        __syncthreads();
        float* sc = (float*)smem;
#pragma unroll
        for (int i = 0; i < 4; ++i) {
            const int lr = wRow + i * 16 + (lane >> 2);
#pragma unroll
            for (int j = 0; j < 8; ++j) {
                const int lc = wCol + j * 8 + (lane & 3) * 2;
                sc[(lr    ) * 129 + lc    ] = acc[i][j][0];
                sc[(lr    ) * 129 + lc + 1] = acc[i][j][1];
                sc[(lr + 8) * 129 + lc    ] = acc[i][j][2];
                sc[(lr + 8) * 129 + lc + 1] = acc[i][j][3];
            }
        }
        __syncthreads();
        for (int cc = 0; cc < 128; ++cc) {
            __nv_bfloat16 b = __float2bfloat16(sc[tid * 129 + cc]);
            C[(size_t)(colBase + cc) * N_PTS + rowBase + tid] = *(unsigned short*)&b;
        }
    }
}

// ---------------- fp16 single-pass GEMM: C = A*B^T + bias -------------------
// omode 0: fp32 out; omode 1: fp16 out (packed pairs). relu optional.
__global__ __launch_bounds__(128, 2)
void gemm_f16(const __half* __restrict__ A, const __half* __restrict__ B,
              float* __restrict__ Cf, unsigned short* __restrict__ C16,
              int M, int Nc, int Kd, const float* __restrict__ bias,
              int relu, int omode)
{
    const int bx = blockIdx.x, by = blockIdx.y;
    extern __shared__ char smem[];
    const uint32_t sb = smem_to_u32(smem);
    const int tid = threadIdx.x;
    const int lane = tid & 31;
    const int wid = tid >> 5;
    const int wm = wid & 1;
    const int wn = wid >> 1;
    const int wRow = wm * 64, wCol = wn * 64;

    const int rowBase = by * 128;
    const int colBase = bx * 128;
    const int nchunk = Kd / 64;

    float acc[4][8][4];
#pragma unroll
    for (int i = 0; i < 4; ++i)
#pragma unroll
        for (int j = 0; j < 8; ++j)
#pragma unroll
            for (int q = 0; q < 4; ++q) acc[i][j][q] = 0.f;

    auto load_chunk = [&](int c) {
        const int k0 = c * 64;
        const uint32_t base = sb + (uint32_t)(c & 1) * 32768u;
#pragma unroll
        for (int i = 0; i < 8; ++i) {
            const int u = tid + i * 128;
            const int r = u >> 3, ku = u & 7;
            const int grow = rowBase + r;
            cp_async16(base + (uint32_t)(r * 8 + (ku ^ (r & 7))) * 16,
                       A + (size_t)grow * Kd + k0 + ku * 8, grow < M);
        }
#pragma unroll
        for (int i = 0; i < 8; ++i) {
            const int u = tid + i * 128;
            const int r = u >> 3, ku = u & 7;
            const int grow = colBase + r;
            cp_async16(base + 16384u + (uint32_t)(r * 8 + (ku ^ (r & 7))) * 16,
                       B + (size_t)grow * Kd + k0 + ku * 8, grow < Nc);
        }
        cp_commit();
    };

    load_chunk(0);

    for (int c = 0; c < nchunk; ++c) {
        if (c + 1 < nchunk) { load_chunk(c + 1); cp_wait<1>(); }
        else                { cp_wait<0>(); }
        __syncthreads();

        const uint32_t base = sb + (uint32_t)(c & 1) * 32768u;
#pragma unroll
        for (int s = 0; s < 4; ++s) {
            uint32_t a[4][4];
#pragma unroll
            for (int i = 0; i < 4; ++i) {
                const int r = wRow + i * 16 + (lane & 15);
                const int ku = s * 2 + (lane >> 4);
                ldm_x4(a[i], base + (uint32_t)(r * 8 + (ku ^ (r & 7))) * 16);
            }
            uint32_t bf[4][4];
#pragma unroll
            for (int j = 0; j < 4; ++j) {
                const int rn = wCol + j * 16 + (lane & 7) + ((lane >> 4) << 3);
                const int ku = s * 2 + ((lane >> 3) & 1);
                ldm_x4(bf[j], base + 16384u + (uint32_t)(rn * 8 + (ku ^ (rn & 7))) * 16);
            }
#pragma unroll
            for (int i = 0; i < 4; ++i)
#pragma unroll
                for (int j = 0; j < 4; ++j) {
                    mma16816_f16(acc[i][j * 2 + 0], a[i], bf[j][0], bf[j][1]);
                    mma16816_f16(acc[i][j * 2 + 1], a[i], bf[j][2], bf[j][3]);
                }
        }
        __syncthreads();
    }

#pragma unroll
    for (int i = 0; i < 4; ++i) {
        const int row = rowBase + wRow + i * 16 + (lane >> 2);
#pragma unroll
        for (int j = 0; j < 8; ++j) {
            const int col = colBase + wCol + j * 8 + (lane & 3) * 2;
#pragma unroll
            for (int h = 0; h < 2; ++h) {
                const int rr = row + h * 8;
                if (rr < M) {
                    float v0 = acc[i][j][h * 2 + 0];
                    float v1 = acc[i][j][h * 2 + 1];
                    if (bias) {
                        if (col     < Nc) v0 += __ldg(bias + col);
                        if (col + 1 < Nc) v1 += __ldg(bias + col + 1);
                    }
                    if (relu) { v0 = fmaxf(v0, 0.f); v1 = fmaxf(v1, 0.f); }
                    if (omode == 0) {
                        if (col     < Nc) Cf[(size_t)rr * Nc + col]     = v0;
                        if (col + 1 < Nc) Cf[(size_t)rr * Nc + col + 1] = v1;
                    } else if (col + 1 <= Nc - 1) {
                        __half p0 = __float2half(v0), p1 = __float2half(v1);
                        uint32_t pk = (uint32_t)(*(unsigned short*)&p0) |
                                      ((uint32_t)(*(unsigned short*)&p1) << 16);
                        *(uint32_t*)(C16 + (size_t)rr * Nc + col) = pk;
                    }
                }
            }
        }
    }
}

// ---------------- bf16x3 GEMM (classifier): C = A*B^T, hi/lo splits ---------
__global__ __launch_bounds__(128, 2)
void gemm_bf3(const __nv_bfloat16* __restrict__ Ah, const __nv_bfloat16* __restrict__ Al,
              const __nv_bfloat16* __restrict__ Bh, const __nv_bfloat16* __restrict__ Bl,
              float* __restrict__ Cf, int M, int Nc, int Kd)
{
    const int bx = blockIdx.x, by = blockIdx.y;
    extern __shared__ char smem[];
    const uint32_t sb = smem_to_u32(smem);
    const int tid = threadIdx.x;
    const int lane = tid & 31;
    const int wid = tid >> 5;
    const int wm = wid & 1;
    const int wn = wid >> 1;
    const int wRow = wm * 64, wCol = wn * 64;

    const int rowBase = by * 128;
    const int colBase = bx * 128;
    const int kcount = Kd / 64;
    const int nchunk = 3 * kcount;

    float acc[4][8][4];
#pragma unroll
    for (int i = 0; i < 4; ++i)
#pragma unroll
        for (int j = 0; j < 8; ++j)
#pragma unroll
            for (int q = 0; q < 4; ++q) acc[i][j][q] = 0.f;

    auto load_chunk = [&](int c) {
        const int pass = c / kcount;
        const int k0 = (c % kcount) * 64;
        const __nv_bfloat16* As = (pass == 2) ? Al : Ah;
        const __nv_bfloat16* Bs = (pass == 1) ? Bl : Bh;
        const uint32_t base = sb + (uint32_t)(c & 1) * 32768u;
#pragma unroll
        for (int i = 0; i < 8; ++i) {
            const int u = tid + i * 128;
            const int r = u >> 3, ku = u & 7;
            const int grow = rowBase + r;
            cp_async16(base + (uint32_t)(r * 8 + (ku ^ (r & 7))) * 16,
                       As + (size_t)grow * Kd + k0 + ku * 8, grow < M);
        }
#pragma unroll
        for (int i = 0; i < 8; ++i) {
            const int u = tid + i * 128;
            const int r = u >> 3, ku = u & 7;
            const int grow = colBase + r;
            cp_async16(base + 16384u + (uint32_t)(r * 8 + (ku ^ (r & 7))) * 16,
                       Bs + (size_t)grow * Kd + k0 + ku * 8, grow < Nc);
        }
        cp_commit();
    };

    load_chunk(0);

    for (int c = 0; c < nchunk; ++c) {
        if (c + 1 < nchunk) { load_chunk(c + 1); cp_wait<1>(); }
        else                { cp_wait<0>(); }
        __syncthreads();

        const uint32_t base = sb + (uint32_t)(c & 1) * 32768u;
#pragma unroll
        for (int s = 0; s < 4; ++s) {
            uint32_t a[4][4];
#pragma unroll
            for (int i = 0; i < 4; ++i) {
                const int r = wRow + i * 16 + (lane & 15);
                const int ku = s * 2 + (lane >> 4);
                ldm_x4(a[i], base + (uint32_t)(r * 8 + (ku ^ (r & 7))) * 16);
            }
            uint32_t bf[4][4];
#pragma unroll
            for (int j = 0; j < 4; ++j) {
                const int rn = wCol + j * 16 + (lane & 7) + ((lane >> 4) << 3);
                const int ku = s * 2 + ((lane >> 3) & 1);
                ldm_x4(bf[j], base + 16384u + (uint32_t)(rn * 8 + (ku ^ (rn & 7))) * 16);
            }
#pragma unroll
            for (int i = 0; i < 4; ++i)
#pragma unroll
                for (int j = 0; j < 4; ++j) {
                    mma16816_bf(acc[i][j * 2 + 0], a[i], bf[j][0], bf[j][1]);
                    mma16816_bf(acc[i][j * 2 + 1], a[i], bf[j][2], bf[j][3]);
                }
        }
        __syncthreads();
    }

#pragma unroll
    for (int i = 0; i < 4; ++i) {
        const int row = rowBase + wRow + i * 16 + (lane >> 2);
#pragma unroll
        for (int j = 0; j < 8; ++j) {
            const int col = colBase + wCol + j * 8 + (lane & 3) * 2;
#pragma unroll
            for (int h = 0; h < 2; ++h) {
                const int rr = row + h * 8;
                if (rr < M) {
                    if (col     < Nc) Cf[(size_t)rr * Nc + col]     = acc[i][j][h * 2 + 0];
                    if (col + 1 < Nc) Cf[(size_t)rr * Nc + col + 1] = acc[i][j][h * 2 + 1];
                }
            }
        }
    }
}

// ---------------- row L2 normalize (fp32 + fp8 copy) -------------------------
__global__ void normalize_kernel(const float* __restrict__ x) {
    int i = blockIdx.x;
    int tid = threadIdx.x;
    const float* xi = x + (size_t)i * DIM;
    float s = 0.f;
    for (int d = tid; d < DIM; d += 256) { float v = xi[d]; s += v * v; }
    __shared__ float sh[256];
    sh[tid] = s; __syncthreads();
    for (int o = 128; o > 0; o >>= 1) {
        if (tid < o) sh[tid] += sh[tid + o];
        __syncthreads();
    }
    float inv = 1.f / fmaxf(sqrtf(sh[0]), 1e-12f);
    float* out = g_xn + (size_t)i * DIM;
    unsigned char* out8 = g_x8 + (size_t)i * DIM;
    for (int d = tid; d < DIM; d += 256) {
        float v = xi[d] * inv;
        out[d] = v;
        out8[d] = (unsigned char)__nv_cvt_float_to_fp8(v * FP8_SCALE,
                                                       __NV_SATFINITE, __NV_E4M3);
    }
}

// ---------------- fp16 weight convert ----------------------------------------
__global__ void conv16_kernel(const float* __restrict__ src,
                              unsigned short* __restrict__ dst, size_t n) {
    size_t i = (size_t)blockIdx.x * 256 + threadIdx.x;
    if (i >= n) return;
    __half h = __float2half(src[i]);
    dst[i] = *(unsigned short*)&h;
}

// ---------------- bf16 hi/lo split (classifier weights) ----------------------
__global__ void split_kernel(const float* __restrict__ src,
                             unsigned short* __restrict__ hi,
                             unsigned short* __restrict__ lo, size_t n) {
    size_t i = (size_t)blockIdx.x * 256 + threadIdx.x;
    if (i >= n) return;
    float v = src[i];
    __nv_bfloat16 h = __float2bfloat16(v);
    ((__nv_bfloat16*)hi)[i] = h;
    ((__nv_bfloat16*)lo)[i] = __float2bfloat16(v - __bfloat162float(h));
}

// ---------------- radix-select exact per-row top-16 (bf16 sims) --------------
#define TK_THREADS 256
#define TK_BUF 1024

__global__ __launch_bounds__(TK_THREADS)
void topk_kernel() {
    const int i = blockIdx.x;
    const int tid = threadIdx.x;
    const int wid = tid >> 5, lane = tid & 31;
    const uint4* row4 = (const uint4*)(g_sim + (size_t)i * N_PTS);

    __shared__ int hist[8 * 264];
    __shared__ int hist2[256];
    __shared__ uint32_t buf[TK_BUF];
    __shared__ int nbuf;
    __shared__ int s_b, s_cntAbove;
    __shared__ uint32_t s_T;

    for (int b = tid; b < 8 * 264; b += TK_THREADS) hist[b] = 0;
    for (int b = tid; b < 256; b += TK_THREADS) hist2[b] = 0;
    if (tid == 0) nbuf = 0;
    __syncthreads();

    int* myh = hist + wid * 264;
    for (int j16 = tid; j16 < N_PTS / 8; j16 += TK_THREADS) {
        uint4 u = row4[j16];
        uint32_t w[4] = {u.x, u.y, u.z, u.w};
#pragma unroll
        for (int q = 0; q < 4; ++q) {
#pragma unroll
            for (int e = 0; e < 2; ++e) {
                uint32_t k = sortable16((w[q] >> (e * 16)) & 0xFFFFu);
                atomicAdd(&myh[k >> 8], 1);
            }
        }
    }
    __syncthreads();
    for (int b = tid; b < 256; b += TK_THREADS) {
        int s = 0;
#pragma unroll
        for (int w = 0; w < 8; ++w) s += hist[w * 264 + b];
        hist[b] = s;
    }
    __syncthreads();
    if (tid == 0) {
        int cum = 0, b = 255;
        for (; b > 0; --b) {
            if (cum + hist[b] >= CAND) break;
            cum += hist[b];
        }
        s_b = b; s_cntAbove = cum;
    }
    __syncthreads();
    const uint32_t bstar = (uint32_t)s_b;

    for (int j16 = tid; j16 < N_PTS / 8; j16 += TK_THREADS) {
        uint4 u = row4[j16];
        uint32_t w[4] = {u.x, u.y, u.z, u.w};
#pragma unroll
        for (int q = 0; q < 4; ++q) {
#pragma unroll
            for (int e = 0; e < 2; ++e) {
                uint32_t k = sortable16((w[q] >> (e * 16)) & 0xFFFFu);
                if ((k >> 8) == bstar) atomicAdd(&hist2[k & 0xFFu], 1);
            }
        }
    }
    __syncthreads();
    if (tid == 0) {
        int cum = s_cntAbove, s = 255;
        for (; s > 0; --s) {
            if (cum + hist2[s] >= CAND) break;
            cum += hist2[s];
        }
        s_T = (bstar << 8) | (uint32_t)s;
    }
    __syncthreads();
    const uint32_t T = s_T;

    for (int j16 = tid; j16 < N_PTS / 8; j16 += TK_THREADS) {
        uint4 u = row4[j16];
        uint32_t w[4] = {u.x, u.y, u.z, u.w};
#pragma unroll
        for (int q = 0; q < 4; ++q) {
#pragma unroll
            for (int e = 0; e < 2; ++e) {
                uint32_t k = sortable16((w[q] >> (e * 16)) & 0xFFFFu);
                if (k >= T) {
                    int p = atomicAdd(&nbuf, 1);
                    if (p < TK_BUF) {
                        int j = j16 * 8 + q * 2 + e;
                        buf[p] = (k << 16) | (uint32_t)(8191 - j);
                    }
                }
            }
        }
    }
    __syncthreads();

    if (wid == 0) {
        int count = min(nbuf, TK_BUF);
        for (int r = 0; r < CAND; ++r) {
            uint32_t best = 0; int bp = -1;
            for (int p = lane; p < count; p += 32)
                if (buf[p] > best) { best = buf[p]; bp = p; }
#pragma unroll
            for (int o = 16; o > 0; o >>= 1) {
                uint32_t ob = __shfl_xor_sync(0xffffffffu, best, o);
                int      op = __shfl_xor_sync(0xffffffffu, bp, o);
                if (ob > best) { best = ob; bp = op; }
            }
            if (lane == 0) {
                g_cand[(size_t)i * CAND + r] = 8191 - (int)(best & 0xFFFFu);
                buf[bp] = 0;
            }
            __syncwarp();
        }
    }
}

// ---------------- exact fp32 rescore of 16 candidates -> top-6 ---------------
__device__ __forceinline__ bool better(float v1, int i1, float v2, int i2) {
    return (v1 > v2) || (v1 == v2 && i1 < i2);
}

__global__ void rescore_kernel() {
    int i = blockIdx.x;
    int tid = threadIdx.x;
    int wid = tid >> 5, lane = tid & 31;
    __shared__ float xi[DIM];
    __shared__ int cand[CAND];
    __shared__ float red[CAND][8];
    for (int d = tid; d < DIM; d += 256) xi[d] = g_xn[(size_t)i * DIM + d];
    if (tid < CAND) cand[tid] = g_cand[(size_t)i * CAND + tid];
    __syncthreads();

    float acc[CAND];
#pragma unroll
    for (int c = 0; c < CAND; ++c) acc[c] = 0.f;
    for (int d = tid; d < DIM; d += 256) {
        float xv = xi[d];
#pragma unroll
        for (int c = 0; c < CAND; ++c)
            acc[c] += xv * g_xn[(size_t)cand[c] * DIM + d];
    }
#pragma unroll
    for (int c = 0; c < CAND; ++c) {
#pragma unroll
        for (int o = 16; o > 0; o >>= 1)
            acc[c] += __shfl_xor_sync(0xffffffffu, acc[c], o);
        if (lane == 0) red[c][wid] = acc[c];
    }
    __syncthreads();
    if (tid == 0) {
        float cv[CAND]; int ci[CAND];
#pragma unroll
        for (int c = 0; c < CAND; ++c) {
            float s = 0.f;
#pragma unroll
            for (int w = 0; w < 8; ++w) s += red[c][w];
            cv[c] = s; ci[c] = cand[c];
        }
        for (int r = 0; r < KNN; ++r) {
            int bp = r;
            for (int c = r + 1; c < CAND; ++c)
                if (better(cv[c], ci[c], cv[bp], ci[bp])) bp = c;
            float tv = cv[r]; cv[r] = cv[bp]; cv[bp] = tv;
            int   ti = ci[r]; ci[r] = ci[bp]; ci[bp] = ti;
            g_idx[(size_t)i * KNN + r] = ci[r];
        }
    }
}

// ---------------- k-reciprocal + GIN aggregation -> h0 fp16 ------------------
__global__ void aggr_kernel(const float* __restrict__ x) {
    int i = blockIdx.x;
    int tid = threadIdx.x;
    __shared__ int nb[KNN];
    __shared__ int ok[KNN];
    if (tid < KNN) {
        int j = g_idx[(size_t)i * KNN + tid];
        nb[tid] = j;
        int r = 0;
#pragma unroll
        for (int t = 0; t < KNN; ++t) r |= (g_idx[(size_t)j * KNN + t] == i);
        ok[tid] = r;
    }
    __syncthreads();
    for (int d = tid; d < DIM; d += 256) {
        float acc = GIN_ONE_PLUS_EPS * x[(size_t)i * DIM + d];
#pragma unroll
        for (int c = 0; c < KNN; ++c)
            if (ok[c]) acc += x[(size_t)nb[c] * DIM + d];
        __half h = __float2half(acc);
        g_sh[(size_t)i * DIM + d] = *(unsigned short*)&h;
    }
}

// ---------------- BatchNorm (training-mode batch stats) ----------------------
__global__ void bn_zero_kernel() {
    int c = blockIdx.x * 256 + threadIdx.x;
    if (c < DIM) { g_scale[c] = 0.f; g_shift[c] = 0.f; }
}

__global__ void bn_stats_kernel() {
    int c  = blockIdx.x * 256 + threadIdx.x;
    int r0 = blockIdx.y * 256;
    float s = 0.f, q = 0.f;
    for (int r = r0; r < r0 + 256; ++r) {
        float v = g_h2[(size_t)r * DIM + c];
        s += v; q += v * v;
    }
    atomicAdd(&g_scale[c], s);
    atomicAdd(&g_shift[c], q);
}

__global__ void bn_finalize_kernel(const float* __restrict__ gamma,
                                   const float* __restrict__ beta) {
    int c = blockIdx.x * 256 + threadIdx.x;
    if (c >= DIM) return;
    const float invN = 1.f / (float)N_PTS;
    float mean = g_scale[c] * invN;
    float var  = g_shift[c] * invN - mean * mean;
    float sc   = gamma[c] * rsqrtf(var + BN_EPS);
    g_scale[c] = sc;
    g_shift[c] = beta[c] - mean * sc;
}

// bn apply -> hn bf16 hi/lo splits (for bf16x3 classifier)
__global__ void bn_apply_kernel() {
    size_t idx = (size_t)blockIdx.x * 256 + threadIdx.x;
    int c = (int)(idx & (DIM - 1));
    float v = g_h2[idx] * g_scale[c] + g_shift[c];
    __nv_bfloat16 h = __float2bfloat16(v);
    ((__nv_bfloat16*)g_sh)[idx] = h;
    ((__nv_bfloat16*)g_sl)[idx] = __float2bfloat16(v - __bfloat162float(h));
}

// ---------------- launch -----------------------------------------------------
extern "C" void kernel_launch(void* const* d_in, const int* in_sizes, int n_in,
                              void* d_out, int out_size) {
    const float* x     = (const float*)d_in[0];
    const float* w1    = (const float*)d_in[1];
    const float* b1    = (const float*)d_in[2];
    const float* w2    = (const float*)d_in[3];
    const float* b2    = (const float*)d_in[4];
    const float* gamma = (const float*)d_in[5];
    const float* beta  = (const float*)d_in[6];
    const float* wc    = (const float*)d_in[7];
    float* out = (float*)d_out;

    cudaFuncSetAttribute(gemm_f16, cudaFuncAttributeMaxDynamicSharedMemorySize, SMEM_GEMM);
    cudaFuncSetAttribute(gemm_bf3, cudaFuncAttributeMaxDynamicSharedMemorySize, SMEM_GEMM);
    cudaFuncSetAttribute(sim_fp8,  cudaFuncAttributeMaxDynamicSharedMemorySize, SMEM_GEMM);

    float *p_xn, *p_h2;
    unsigned char* p_x8;
    unsigned short *p_sim, *p_sh, *p_sl, *p_th, *p_w1f, *p_w2f, *p_wch, *p_wcl;
    cudaGetSymbolAddress((void**)&p_xn,  g_xn);
    cudaGetSymbolAddress((void**)&p_x8,  g_x8);
    cudaGetSymbolAddress((void**)&p_sim, g_sim);
    cudaGetSymbolAddress((void**)&p_h2,  g_h2);
    cudaGetSymbolAddress((void**)&p_sh,  g_sh);
    cudaGetSymbolAddress((void**)&p_sl,  g_sl);
    cudaGetSymbolAddress((void**)&p_th,  g_th);
    cudaGetSymbolAddress((void**)&p_w1f, g_w1f);
    cudaGetSymbolAddress((void**)&p_w2f, g_w2f);
    cudaGetSymbolAddress((void**)&p_wch, g_wch);
    cudaGetSymbolAddress((void**)&p_wcl, g_wcl);

    const size_t nDD = (size_t)DIM * DIM;
    const size_t nCD = (size_t)NCLS * DIM;
    const size_t nND = (size_t)N_PTS * DIM;

    normalize_kernel<<<N_PTS, 256>>>(x);
    conv16_kernel<<<(unsigned)((nDD + 255) / 256), 256>>>(w1, p_w1f, nDD);
    conv16_kernel<<<(unsigned)((nDD + 255) / 256), 256>>>(w2, p_w2f, nDD);

    // similarity (fp8 e4m3 HMMA, symmetric, bf16 raw-scale sims)
    sim_fp8<<<dim3(64, 64), 128, SMEM_GEMM>>>(p_x8, p_sim);

    split_kernel<<<(unsigned)((nCD + 255) / 256), 256>>>(wc, p_wch, p_wcl, nCD);

    // radix-select top-16 candidates, exact fp32 rescore -> top-6
    topk_kernel<<<N_PTS, TK_THREADS>>>();
    rescore_kernel<<<N_PTS, 256>>>();

    // k-reciprocal + GIN aggregation -> h0 fp16
    aggr_kernel<<<N_PTS, 256>>>(x);

    // MLP layer 1 (fp16): relu(h0 @ w1^T + b1) -> h1 fp16
    gemm_f16<<<dim3(16, 64), 128, SMEM_GEMM>>>(
        (const __half*)p_sh, (const __half*)p_w1f,
        nullptr, p_th, N_PTS, DIM, DIM, b1, 1, 1);

    // MLP layer 2 (fp16): h1 @ w2^T + b2 -> h2 fp32
    gemm_f16<<<dim3(16, 64), 128, SMEM_GEMM>>>(
        (const __half*)p_th, (const __half*)p_w2f,
        p_h2, nullptr, N_PTS, DIM, DIM, b2, 0, 0);

    // BatchNorm -> hn bf16 splits
    bn_zero_kernel<<<(DIM + 255) / 256, 256>>>();
    bn_stats_kernel<<<dim3(DIM / 256, N_PTS / 256), 256>>>();
    bn_finalize_kernel<<<(DIM + 255) / 256, 256>>>(gamma, beta);
    bn_apply_kernel<<<(unsigned)(nND / 256), 256>>>();

    // classifier (bf16x3, exact): hn @ wc^T -> out [8192, 751]
    gemm_bf3<<<dim3((NCLS + 127) / 128, 64), 128, SMEM_GEMM>>>(
        (const __nv_bfloat16*)p_sh, (const __nv_bfloat16*)p_sl,
        (const __nv_bfloat16*)p_wch, (const __nv_bfloat16*)p_wcl,
        out, N_PTS, NCLS, DIM);
}

// round 16
// speedup vs baseline: 1.7823x; 1.1550x over previous
#include <cuda_runtime.h>
#include <cuda_bf16.h>
#include <cuda_fp16.h>
#include <cuda_fp8.h>
#include <cstdint>
#include <math.h>

#define N_PTS 8192
#define DIM   2048
#define NCLS  751
#define KNN   6
#define CAND  16
#define GIN_ONE_PLUS_EPS 1.3f
#define BN_EPS 1e-5f
#define FP8_SCALE 256.0f

// ---------------- scratch ----------------------------------------------------
__device__ float g_xn [(size_t)N_PTS * DIM];
__device__ unsigned char g_x8 [(size_t)N_PTS * DIM];      // e4m3 of xn*256
__device__ unsigned short g_sim[(size_t)N_PTS * N_PTS];   // bf16 sims (raw scale)
__device__ int   g_cand[(size_t)N_PTS * CAND];
__device__ int   g_idx[(size_t)N_PTS * KNN];
__device__ float g_h2 [(size_t)N_PTS * DIM];
__device__ unsigned short g_sh [(size_t)N_PTS * DIM];     // h0 fp16; later hn fp16
__device__ unsigned short g_th [(size_t)N_PTS * DIM];     // h1 fp16
__device__ unsigned short g_w1f[(size_t)DIM * DIM];       // w1 fp16
__device__ unsigned short g_w2f[(size_t)DIM * DIM];       // w2 fp16
__device__ unsigned short g_wcf[(size_t)NCLS * DIM];      // wc fp16
__device__ float g_scale[DIM];
__device__ float g_shift[DIM];

// ---------------- helpers ----------------------------------------------------
__device__ __forceinline__ uint32_t smem_to_u32(const void* p) {
    uint32_t a;
    asm("{ .reg .u64 t; cvta.to.shared.u64 t, %1; cvt.u32.u64 %0, t; }" : "=r"(a) : "l"(p));
    return a;
}

__device__ __forceinline__ void cp_async16(uint32_t dst, const void* src, int valid) {
    asm volatile("cp.async.cg.shared.global [%0], [%1], 16, %2;"
                 :: "r"(dst), "l"(src), "r"(valid ? 16 : 0) : "memory");
}
__device__ __forceinline__ void cp_commit() {
    asm volatile("cp.async.commit_group;" ::: "memory");
}
template <int N>
__device__ __forceinline__ void cp_wait() {
    asm volatile("cp.async.wait_group %0;" :: "n"(N) : "memory");
}

__device__ __forceinline__ void ldm_x4(uint32_t* r, uint32_t addr) {
    asm volatile("ldmatrix.sync.aligned.m8n8.x4.shared.b16 {%0,%1,%2,%3}, [%4];"
                 : "=r"(r[0]), "=r"(r[1]), "=r"(r[2]), "=r"(r[3]) : "r"(addr));
}

__device__ __forceinline__ void mma16816_f16(float* d, const uint32_t* a, uint32_t b0, uint32_t b1) {
    asm volatile("mma.sync.aligned.m16n8k16.row.col.f32.f16.f16.f32 "
                 "{%0,%1,%2,%3}, {%4,%5,%6,%7}, {%8,%9}, {%0,%1,%2,%3};"
                 : "+f"(d[0]), "+f"(d[1]), "+f"(d[2]), "+f"(d[3])
                 : "r"(a[0]), "r"(a[1]), "r"(a[2]), "r"(a[3]), "r"(b0), "r"(b1));
}

__device__ __forceinline__ void mma16832_fp8(float* d, const uint32_t* a, uint32_t b0, uint32_t b1) {
    asm volatile("mma.sync.aligned.m16n8k32.row.col.f32.e4m3.e4m3.f32 "
                 "{%0,%1,%2,%3}, {%4,%5,%6,%7}, {%8,%9}, {%0,%1,%2,%3};"
                 : "+f"(d[0]), "+f"(d[1]), "+f"(d[2]), "+f"(d[3])
                 : "r"(a[0]), "r"(a[1]), "r"(a[2]), "r"(a[3]), "r"(b0), "r"(b1));
}

// bf16 bit pattern -> order-preserving 16-bit key (bigger = larger value)
__device__ __forceinline__ uint32_t sortable16(uint32_t us) {
    return (us & 0x8000u) ? (~us & 0xFFFFu) : (us | 0x8000u);
}

#define SMEM_GEMM 66048   // max(2*32768 pipeline, 128*129*4 transpose stage)

// ---------------- fp8 similarity GEMM: C = X*X^T (bf16 out, raw scale) -------
// 128x128 CTA tile, BK=128 fp8 bytes, 128 thr (4 warps 2x2, warp tile 64x64),
// cp.async double buffer, swizzled smem, 2 CTAs/SM. Symmetric.
__global__ __launch_bounds__(128, 2)
void sim_fp8(const unsigned char* __restrict__ X, unsigned short* __restrict__ C)
{
    const int bx = blockIdx.x, by = blockIdx.y;
    if (bx > by) return;

    extern __shared__ char smem[];
    const uint32_t sb = smem_to_u32(smem);
    const int tid = threadIdx.x;
    const int lane = tid & 31;
    const int wid = tid >> 5;
    const int wm = wid & 1;
    const int wn = wid >> 1;
    const int wRow = wm * 64, wCol = wn * 64;

    const int rowBase = by * 128;
    const int colBase = bx * 128;
    const int nchunk = DIM / 128;

    float acc[4][8][4];
#pragma unroll
    for (int i = 0; i < 4; ++i)
#pragma unroll
        for (int j = 0; j < 8; ++j)
#pragma unroll
            for (int q = 0; q < 4; ++q) acc[i][j][q] = 0.f;

    auto load_chunk = [&](int c) {
        const int k0 = c * 128;
        const uint32_t base = sb + (uint32_t)(c & 1) * 32768u;
#pragma unroll
        for (int i = 0; i < 8; ++i) {
            const int u = tid + i * 128;
            const int r = u >> 3, ku = u & 7;
            cp_async16(base + (uint32_t)(r * 8 + (ku ^ (r & 7))) * 16,
                       X + (size_t)(rowBase + r) * DIM + k0 + ku * 16, 1);
        }
#pragma unroll
        for (int i = 0; i < 8; ++i) {
            const int u = tid + i * 128;
            const int r = u >> 3, ku = u & 7;
            cp_async16(base + 16384u + (uint32_t)(r * 8 + (ku ^ (r & 7))) * 16,
                       X + (size_t)(colBase + r) * DIM + k0 + ku * 16, 1);
        }
        cp_commit();
    };

    load_chunk(0);

    for (int c = 0; c < nchunk; ++c) {
        if (c + 1 < nchunk) { load_chunk(c + 1); cp_wait<1>(); }
        else                { cp_wait<0>(); }
        __syncthreads();

        const uint32_t base = sb + (uint32_t)(c & 1) * 32768u;
#pragma unroll
        for (int s = 0; s < 4; ++s) {
            uint32_t a[4][4];
#pragma unroll
            for (int i = 0; i < 4; ++i) {
                const int r = wRow + i * 16 + (lane & 15);
                const int ku = s * 2 + (lane >> 4);
                ldm_x4(a[i], base + (uint32_t)(r * 8 + (ku ^ (r & 7))) * 16);
            }
            uint32_t bf[4][4];
#pragma unroll
            for (int j = 0; j < 4; ++j) {
                const int rn = wCol + j * 16 + (lane & 7) + ((lane >> 4) << 3);
                const int ku = s * 2 + ((lane >> 3) & 1);
                ldm_x4(bf[j], base + 16384u + (uint32_t)(rn * 8 + (ku ^ (rn & 7))) * 16);
            }
#pragma unroll
            for (int i = 0; i < 4; ++i)
#pragma unroll
                for (int j = 0; j < 4; ++j) {
                    mma16832_fp8(acc[i][j * 2 + 0], a[i], bf[j][0], bf[j][1]);
                    mma16832_fp8(acc[i][j * 2 + 1], a[i], bf[j][2], bf[j][3]);
                }
        }
        __syncthreads();
    }

#pragma unroll
    for (int i = 0; i < 4; ++i) {
        const int row = rowBase + wRow + i * 16 + (lane >> 2);
#pragma unroll
        for (int j = 0; j < 8; ++j) {
            const int col = colBase + wCol + j * 8 + (lane & 3) * 2;
#pragma unroll
            for (int h = 0; h < 2; ++h) {
                const int rr = row + h * 8;
                __nv_bfloat16 b0 = __float2bfloat16(acc[i][j][h * 2 + 0]);
                __nv_bfloat16 b1 = __float2bfloat16(acc[i][j][h * 2 + 1]);
                uint32_t pk = (uint32_t)(*(unsigned short*)&b0) |
                              ((uint32_t)(*(unsigned short*)&b1) << 16);
                *(uint32_t*)(C + (size_t)rr * N_PTS + col) = pk;
            }
        }
    }

    if (bx < by) {
        __syncthreads();
        float* sc = (float*)smem;
#pragma unroll
        for (int i = 0; i < 4; ++i) {
            const int lr = wRow + i * 16 + (lane >> 2);
#pragma unroll
            for (int j = 0; j < 8; ++j) {
                const int lc = wCol + j * 8 + (lane & 3) * 2;
                sc[(lr    ) * 129 + lc    ] = acc[i][j][0];
                sc[(lr    ) * 129 + lc + 1] = acc[i][j][1];
                sc[(lr + 8) * 129 + lc    ] = acc[i][j][2];
                sc[(lr + 8) * 129 + lc + 1] = acc[i][j][3];
            }
        }
        __syncthreads();
        for (int cc = 0; cc < 128; ++cc) {
            __nv_bfloat16 b = __float2bfloat16(sc[tid * 129 + cc]);
            C[(size_t)(colBase + cc) * N_PTS + rowBase + tid] = *(unsigned short*)&b;
        }
    }
}

// ---------------- fp16 single-pass GEMM: C = A*B^T + bias -------------------
// omode 0: fp32 out; omode 1: fp16 out (packed pairs). relu optional.
__global__ __launch_bounds__(128, 2)
void gemm_f16(const __half* __restrict__ A, const __half* __restrict__ B,
              float* __restrict__ Cf, unsigned short* __restrict__ C16,
              int M, int Nc, int Kd, const float* __restrict__ bias,
              int relu, int omode)
{
    const int bx = blockIdx.x, by = blockIdx.y;
    extern __shared__ char smem[];
    const uint32_t sb = smem_to_u32(smem);
    const int tid = threadIdx.x;
    const int lane = tid & 31;
    const int wid = tid >> 5;
    const int wm = wid & 1;
    const int wn = wid >> 1;
    const int wRow = wm * 64, wCol = wn * 64;

    const int rowBase = by * 128;
    const int colBase = bx * 128;
    const int nchunk = Kd / 64;

    float acc[4][8][4];
#pragma unroll
    for (int i = 0; i < 4; ++i)
#pragma unroll
        for (int j = 0; j < 8; ++j)
#pragma unroll
            for (int q = 0; q < 4; ++q) acc[i][j][q] = 0.f;

    auto load_chunk = [&](int c) {
        const int k0 = c * 64;
        const uint32_t base = sb + (uint32_t)(c & 1) * 32768u;
#pragma unroll
        for (int i = 0; i < 8; ++i) {
            const int u = tid + i * 128;
            const int r = u >> 3, ku = u & 7;
            const int grow = rowBase + r;
            cp_async16(base + (uint32_t)(r * 8 + (ku ^ (r & 7))) * 16,
                       A + (size_t)grow * Kd + k0 + ku * 8, grow < M);
        }
#pragma unroll
        for (int i = 0; i < 8; ++i) {
            const int u = tid + i * 128;
            const int r = u >> 3, ku = u & 7;
            const int grow = colBase + r;
            cp_async16(base + 16384u + (uint32_t)(r * 8 + (ku ^ (r & 7))) * 16,
                       B + (size_t)grow * Kd + k0 + ku * 8, grow < Nc);
        }
        cp_commit();
    };

    load_chunk(0);

    for (int c = 0; c < nchunk; ++c) {
        if (c + 1 < nchunk) { load_chunk(c + 1); cp_wait<1>(); }
        else                { cp_wait<0>(); }
        __syncthreads();

        const uint32_t base = sb + (uint32_t)(c & 1) * 32768u;
#pragma unroll
        for (int s = 0; s < 4; ++s) {
            uint32_t a[4][4];
#pragma unroll
            for (int i = 0; i < 4; ++i) {
                const int r = wRow + i * 16 + (lane & 15);
                const int ku = s * 2 + (lane >> 4);
                ldm_x4(a[i], base + (uint32_t)(r * 8 + (ku ^ (r & 7))) * 16);
            }
            uint32_t bf[4][4];
#pragma unroll
            for (int j = 0; j < 4; ++j) {
                const int rn = wCol + j * 16 + (lane & 7) + ((lane >> 4) << 3);
                const int ku = s * 2 + ((lane >> 3) & 1);
                ldm_x4(bf[j], base + 16384u + (uint32_t)(rn * 8 + (ku ^ (rn & 7))) * 16);
            }
#pragma unroll
            for (int i = 0; i < 4; ++i)
#pragma unroll
                for (int j = 0; j < 4; ++j) {
                    mma16816_f16(acc[i][j * 2 + 0], a[i], bf[j][0], bf[j][1]);
                    mma16816_f16(acc[i][j * 2 + 1], a[i], bf[j][2], bf[j][3]);
                }
        }
        __syncthreads();
    }

#pragma unroll
    for (int i = 0; i < 4; ++i) {
        const int row = rowBase + wRow + i * 16 + (lane >> 2);
#pragma unroll
        for (int j = 0; j < 8; ++j) {
            const int col = colBase + wCol + j * 8 + (lane & 3) * 2;
#pragma unroll
            for (int h = 0; h < 2; ++h) {
                const int rr = row + h * 8;
                if (rr < M) {
                    float v0 = acc[i][j][h * 2 + 0];
                    float v1 = acc[i][j][h * 2 + 1];
                    if (bias) {
                        if (col     < Nc) v0 += __ldg(bias + col);
                        if (col + 1 < Nc) v1 += __ldg(bias + col + 1);
                    }
                    if (relu) { v0 = fmaxf(v0, 0.f); v1 = fmaxf(v1, 0.f); }
                    if (omode == 0) {
                        if (col     < Nc) Cf[(size_t)rr * Nc + col]     = v0;
                        if (col + 1 < Nc) Cf[(size_t)rr * Nc + col + 1] = v1;
                    } else if (col + 1 <= Nc - 1) {
                        __half p0 = __float2half(v0), p1 = __float2half(v1);
                        uint32_t pk = (uint32_t)(*(unsigned short*)&p0) |
                                      ((uint32_t)(*(unsigned short*)&p1) << 16);
                        *(uint32_t*)(C16 + (size_t)rr * Nc + col) = pk;
                    }
                }
            }
        }
    }
}

// ---------------- row L2 normalize (fp32 + fp8 copy) -------------------------
__global__ void normalize_kernel(const float* __restrict__ x) {
    int i = blockIdx.x;
    int tid = threadIdx.x;
    const float* xi = x + (size_t)i * DIM;
    float s = 0.f;
    for (int d = tid; d < DIM; d += 256) { float v = xi[d]; s += v * v; }
    __shared__ float sh[256];
    sh[tid] = s; __syncthreads();
    for (int o = 128; o > 0; o >>= 1) {
        if (tid < o) sh[tid] += sh[tid + o];
        __syncthreads();
    }
    float inv = 1.f / fmaxf(sqrtf(sh[0]), 1e-12f);
    float* out = g_xn + (size_t)i * DIM;
    unsigned char* out8 = g_x8 + (size_t)i * DIM;
    for (int d = tid; d < DIM; d += 256) {
        float v = xi[d] * inv;
        out[d] = v;
        out8[d] = (unsigned char)__nv_cvt_float_to_fp8(v * FP8_SCALE,
                                                       __NV_SATFINITE, __NV_E4M3);
    }
}

// ---------------- fp16 weight convert ----------------------------------------
__global__ void conv16_kernel(const float* __restrict__ src,
                              unsigned short* __restrict__ dst, size_t n) {
    size_t i = (size_t)blockIdx.x * 256 + threadIdx.x;
    if (i >= n) return;
    __half h = __float2half(src[i]);
    dst[i] = *(unsigned short*)&h;
}

// ---------------- radix-select exact per-row top-16 (bf16 sims) --------------
#define TK_THREADS 256
#define TK_BUF 1024

__global__ __launch_bounds__(TK_THREADS)
void topk_kernel() {
    const int i = blockIdx.x;
    const int tid = threadIdx.x;
    const int wid = tid >> 5, lane = tid & 31;
    const uint4* row4 = (const uint4*)(g_sim + (size_t)i * N_PTS);

    __shared__ int hist[8 * 264];
    __shared__ int hist2[256];
    __shared__ uint32_t buf[TK_BUF];
    __shared__ int nbuf;
    __shared__ int s_b, s_cntAbove;
    __shared__ uint32_t s_T;

    for (int b = tid; b < 8 * 264; b += TK_THREADS) hist[b] = 0;
    for (int b = tid; b < 256; b += TK_THREADS) hist2[b] = 0;
    if (tid == 0) nbuf = 0;
    __syncthreads();

    int* myh = hist + wid * 264;
    for (int j16 = tid; j16 < N_PTS / 8; j16 += TK_THREADS) {
        uint4 u = row4[j16];
        uint32_t w[4] = {u.x, u.y, u.z, u.w};
#pragma unroll
        for (int q = 0; q < 4; ++q) {
#pragma unroll
            for (int e = 0; e < 2; ++e) {
                uint32_t k = sortable16((w[q] >> (e * 16)) & 0xFFFFu);
                atomicAdd(&myh[k >> 8], 1);
            }
        }
    }
    __syncthreads();
    for (int b = tid; b < 256; b += TK_THREADS) {
        int s = 0;
#pragma unroll
        for (int w = 0; w < 8; ++w) s += hist[w * 264 + b];
        hist[b] = s;
    }
    __syncthreads();
    if (tid == 0) {
        int cum = 0, b = 255;
        for (; b > 0; --b) {
            if (cum + hist[b] >= CAND) break;
            cum += hist[b];
        }
        s_b = b; s_cntAbove = cum;
    }
    __syncthreads();
    const uint32_t bstar = (uint32_t)s_b;

    for (int j16 = tid; j16 < N_PTS / 8; j16 += TK_THREADS) {
        uint4 u = row4[j16];
        uint32_t w[4] = {u.x, u.y, u.z, u.w};
#pragma unroll
        for (int q = 0; q < 4; ++q) {
#pragma unroll
            for (int e = 0; e < 2; ++e) {
                uint32_t k = sortable16((w[q] >> (e * 16)) & 0xFFFFu);
                if ((k >> 8) == bstar) atomicAdd(&hist2[k & 0xFFu], 1);
            }
        }
    }
    __syncthreads();
    if (tid == 0) {
        int cum = s_cntAbove, s = 255;
        for (; s > 0; --s) {
            if (cum + hist2[s] >= CAND) break;
            cum += hist2[s];
        }
        s_T = (bstar << 8) | (uint32_t)s;
    }
    __syncthreads();
    const uint32_t T = s_T;

    for (int j16 = tid; j16 < N_PTS / 8; j16 += TK_THREADS) {
        uint4 u = row4[j16];
        uint32_t w[4] = {u.x, u.y, u.z, u.w};
#pragma unroll
        for (int q = 0; q < 4; ++q) {
#pragma unroll
            for (int e = 0; e < 2; ++e) {
                uint32_t k = sortable16((w[q] >> (e * 16)) & 0xFFFFu);
                if (k >= T) {
                    int p = atomicAdd(&nbuf, 1);
                    if (p < TK_BUF) {
                        int j = j16 * 8 + q * 2 + e;
                        buf[p] = (k << 16) | (uint32_t)(8191 - j);
                    }
                }
            }
        }
    }
    __syncthreads();

    if (wid == 0) {
        int count = min(nbuf, TK_BUF);
        for (int r = 0; r < CAND; ++r) {
            uint32_t best = 0; int bp = -1;
            for (int p = lane; p < count; p += 32)
                if (buf[p] > best) { best = buf[p]; bp = p; }
#pragma unroll
            for (int o = 16; o > 0; o >>= 1) {
                uint32_t ob = __shfl_xor_sync(0xffffffffu, best, o);
                int      op = __shfl_xor_sync(0xffffffffu, bp, o);
                if (ob > best) { best = ob; bp = op; }
            }
            if (lane == 0) {
                g_cand[(size_t)i * CAND + r] = 8191 - (int)(best & 0xFFFFu);
                buf[bp] = 0;
            }
            __syncwarp();
        }
    }
}

// ---------------- exact fp32 rescore of 16 candidates -> top-6 ---------------
__device__ __forceinline__ bool better(float v1, int i1, float v2, int i2) {
    return (v1 > v2) || (v1 == v2 && i1 < i2);
}

__global__ void rescore_kernel() {
    int i = blockIdx.x;
    int tid = threadIdx.x;
    int wid = tid >> 5, lane = tid & 31;
    __shared__ float xi[DIM];
    __shared__ int cand[CAND];
    __shared__ float red[CAND][8];
    for (int d = tid; d < DIM; d += 256) xi[d] = g_xn[(size_t)i * DIM + d];
    if (tid < CAND) cand[tid] = g_cand[(size_t)i * CAND + tid];
    __syncthreads();

    float acc[CAND];
#pragma unroll
    for (int c = 0; c < CAND; ++c) acc[c] = 0.f;
    for (int d = tid; d < DIM; d += 256) {
        float xv = xi[d];
#pragma unroll
        for (int c = 0; c < CAND; ++c)
            acc[c] += xv * g_xn[(size_t)cand[c] * DIM + d];
    }
#pragma unroll
    for (int c = 0; c < CAND; ++c) {
#pragma unroll
        for (int o = 16; o > 0; o >>= 1)
            acc[c] += __shfl_xor_sync(0xffffffffu, acc[c], o);
        if (lane == 0) red[c][wid] = acc[c];
    }
    __syncthreads();
    if (tid == 0) {
        float cv[CAND]; int ci[CAND];
#pragma unroll
        for (int c = 0; c < CAND; ++c) {
            float s = 0.f;
#pragma unroll
            for (int w = 0; w < 8; ++w) s += red[c][w];
            cv[c] = s; ci[c] = cand[c];
        }
        for (int r = 0; r < KNN; ++r) {
            int bp = r;
            for (int c = r + 1; c < CAND; ++c)
                if (better(cv[c], ci[c], cv[bp], ci[bp])) bp = c;
            float tv = cv[r]; cv[r] = cv[bp]; cv[bp] = tv;
            int   ti = ci[r]; ci[r] = ci[bp]; ci[bp] = ti;
            g_idx[(size_t)i * KNN + r] = ci[r];
        }
    }
}

// ---------------- k-reciprocal + GIN aggregation -> h0 fp16 ------------------
__global__ void aggr_kernel(const float* __restrict__ x) {
    int i = blockIdx.x;
    int tid = threadIdx.x;
    __shared__ int nb[KNN];
    __shared__ int ok[KNN];
    if (tid < KNN) {
        int j = g_idx[(size_t)i * KNN + tid];
        nb[tid] = j;
        int r = 0;
#pragma unroll
        for (int t = 0; t < KNN; ++t) r |= (g_idx[(size_t)j * KNN + t] == i);
        ok[tid] = r;
    }
    __syncthreads();
    for (int d = tid; d < DIM; d += 256) {
        float acc = GIN_ONE_PLUS_EPS * x[(size_t)i * DIM + d];
#pragma unroll
        for (int c = 0; c < KNN; ++c)
            if (ok[c]) acc += x[(size_t)nb[c] * DIM + d];
        __half h = __float2half(acc);
        g_sh[(size_t)i * DIM + d] = *(unsigned short*)&h;
    }
}

// ---------------- BatchNorm (training-mode batch stats) ----------------------
__global__ void bn_zero_kernel() {
    int c = blockIdx.x * 256 + threadIdx.x;
    if (c < DIM) { g_scale[c] = 0.f; g_shift[c] = 0.f; }
}

__global__ void bn_stats_kernel() {
    int c  = blockIdx.x * 256 + threadIdx.x;
    int r0 = blockIdx.y * 256;
    float s = 0.f, q = 0.f;
    for (int r = r0; r < r0 + 256; ++r) {
        float v = g_h2[(size_t)r * DIM + c];
        s += v; q += v * v;
    }
    atomicAdd(&g_scale[c], s);
    atomicAdd(&g_shift[c], q);
}

__global__ void bn_finalize_kernel(const float* __restrict__ gamma,
                                   const float* __restrict__ beta) {
    int c = blockIdx.x * 256 + threadIdx.x;
    if (c >= DIM) return;
    const float invN = 1.f / (float)N_PTS;
    float mean = g_scale[c] * invN;
    float var  = g_shift[c] * invN - mean * mean;
    float sc   = gamma[c] * rsqrtf(var + BN_EPS);
    g_scale[c] = sc;
    g_shift[c] = beta[c] - mean * sc;
}

// bn apply -> hn fp16 (for fp16 classifier)
__global__ void bn_apply_kernel() {
    size_t idx = (size_t)blockIdx.x * 256 + threadIdx.x;
    int c = (int)(idx & (DIM - 1));
    float v = g_h2[idx] * g_scale[c] + g_shift[c];
    __half h = __float2half(v);
    g_sh[idx] = *(unsigned short*)&h;
}

// ---------------- launch -----------------------------------------------------
extern "C" void kernel_launch(void* const* d_in, const int* in_sizes, int n_in,
                              void* d_out, int out_size) {
    const float* x     = (const float*)d_in[0];
    const float* w1    = (const float*)d_in[1];
    const float* b1    = (const float*)d_in[2];
    const float* w2    = (const float*)d_in[3];
    const float* b2    = (const float*)d_in[4];
    const float* gamma = (const float*)d_in[5];
    const float* beta  = (const float*)d_in[6];
    const float* wc    = (const float*)d_in[7];
    float* out = (float*)d_out;

    cudaFuncSetAttribute(gemm_f16, cudaFuncAttributeMaxDynamicSharedMemorySize, SMEM_GEMM);
    cudaFuncSetAttribute(sim_fp8,  cudaFuncAttributeMaxDynamicSharedMemorySize, SMEM_GEMM);

    float *p_xn, *p_h2;
    unsigned char* p_x8;
    unsigned short *p_sim, *p_sh, *p_th, *p_w1f, *p_w2f, *p_wcf;
    cudaGetSymbolAddress((void**)&p_xn,  g_xn);
    cudaGetSymbolAddress((void**)&p_x8,  g_x8);
    cudaGetSymbolAddress((void**)&p_sim, g_sim);
    cudaGetSymbolAddress((void**)&p_h2,  g_h2);
    cudaGetSymbolAddress((void**)&p_sh,  g_sh);
    cudaGetSymbolAddress((void**)&p_th,  g_th);
    cudaGetSymbolAddress((void**)&p_w1f, g_w1f);
    cudaGetSymbolAddress((void**)&p_w2f, g_w2f);
    cudaGetSymbolAddress((void**)&p_wcf, g_wcf);

    const size_t nDD = (size_t)DIM * DIM;
    const size_t nCD = (size_t)NCLS * DIM;
    const size_t nND = (size_t)N_PTS * DIM;

    normalize_kernel<<<N_PTS, 256>>>(x);
    conv16_kernel<<<(unsigned)((nDD + 255) / 256), 256>>>(w1, p_w1f, nDD);
    conv16_kernel<<<(unsigned)((nDD + 255) / 256), 256>>>(w2, p_w2f, nDD);

    // similarity (fp8 e4m3 HMMA, symmetric, bf16 raw-scale sims)
    sim_fp8<<<dim3(64, 64), 128, SMEM_GEMM>>>(p_x8, p_sim);

    conv16_kernel<<<(unsigned)((nCD + 255) / 256), 256>>>(wc, p_wcf, nCD);

    // radix-select top-16 candidates, exact fp32 rescore -> top-6
    topk_kernel<<<N_PTS, TK_THREADS>>>();
    rescore_kernel<<<N_PTS, 256>>>();

    // k-reciprocal + GIN aggregation -> h0 fp16
    aggr_kernel<<<N_PTS, 256>>>(x);

    // MLP layer 1 (fp16): relu(h0 @ w1^T + b1) -> h1 fp16
    gemm_f16<<<dim3(16, 64), 128, SMEM_GEMM>>>(
        (const __half*)p_sh, (const __half*)p_w1f,
        nullptr, p_th, N_PTS, DIM, DIM, b1, 1, 1);

    // MLP layer 2 (fp16): h1 @ w2^T + b2 -> h2 fp32
    gemm_f16<<<dim3(16, 64), 128, SMEM_GEMM>>>(
        (const __half*)p_th, (const __half*)p_w2f,
        p_h2, nullptr, N_PTS, DIM, DIM, b2, 0, 0);

    // BatchNorm -> hn fp16
    bn_zero_kernel<<<(DIM + 255) / 256, 256>>>();
    bn_stats_kernel<<<dim3(DIM / 256, N_PTS / 256), 256>>>();
    bn_finalize_kernel<<<(DIM + 255) / 256, 256>>>(gamma, beta);
    bn_apply_kernel<<<(unsigned)(nND / 256), 256>>>();

    // classifier (fp16): hn @ wc^T -> out [8192, 751]
    gemm_f16<<<dim3((NCLS + 127) / 128, 64), 128, SMEM_GEMM>>>(
        (const __half*)p_sh, (const __half*)p_wcf,
        out, nullptr, N_PTS, NCLS, DIM, nullptr, 0, 0);
}